// round 7
// baseline (speedup 1.0000x reference)
#include <cuda_runtime.h>
#include <math.h>

#define NN 10000
#define EMAX 320000
#define ETMAX (EMAX + NN)

// ---------------- scratch (device globals; no allocation allowed) ----------------
__device__ float    g_hbuf[NN * 1024];   // h of current conv (HC <= 1024)
__device__ float    g_out1[NN * 256];
__device__ float    g_out2[NN * 128];
__device__ float    g_zb  [NN * 64];
__device__ float    g_d1b [NN * 128];
__device__ float    g_d2b [NN * 256];
__device__ float    g_al  [NN * 4];
__device__ float    g_ar  [NN * 4];
__device__ unsigned g_m   [NN * 4];      // encoded running max per (dst, head)
__device__ float    g_den [NN * 4];      // softmax denom -> 1/(4*denom)
__device__ float    g_e   [ETMAX * 4];   // per-edge logits -> exp values
__device__ float    g_sq  [NN];          // row squared norms of recon

// ---------------- helpers ----------------
__device__ __forceinline__ unsigned encf(float f) {
    unsigned u = __float_as_uint(f);
    return (u & 0x80000000u) ? ~u : (u | 0x80000000u);
}
__device__ __forceinline__ float decf(unsigned u) {
    return (u & 0x80000000u) ? __uint_as_float(u ^ 0x80000000u) : __uint_as_float(~u);
}

// ---------------- generic 128x128 SGEMM (NN layout), epi: 0=none,1=+bias,2=+bias,relu ----------------
__global__ void sgemm128(const float* __restrict__ A, const float* __restrict__ B,
                         const float* __restrict__ bias, float* __restrict__ C,
                         int M, int N, int K, int epi)
{
    __shared__ float As[16][128];
    __shared__ float Bs[16][128];
    const int tid = threadIdx.x;
    const int tx = tid & 15, ty = tid >> 4;
    const int rowBase = blockIdx.y * 128, colBase = blockIdx.x * 128;
    float acc[8][8];
#pragma unroll
    for (int i = 0; i < 8; i++)
#pragma unroll
        for (int j = 0; j < 8; j++) acc[i][j] = 0.f;

    for (int k0 = 0; k0 < K; k0 += 16) {
#pragma unroll
        for (int l = 0; l < 2; l++) {
            int i  = tid + l * 256;
            int m  = i >> 2, kk = (i & 3) << 2;
            int gm = rowBase + m;
            float4 v = make_float4(0.f, 0.f, 0.f, 0.f);
            if (gm < M) v = *(const float4*)(A + (size_t)gm * K + k0 + kk);
            As[kk + 0][m] = v.x; As[kk + 1][m] = v.y; As[kk + 2][m] = v.z; As[kk + 3][m] = v.w;
            int kb = i >> 5, n = (i & 31) << 2;
            int gn = colBase + n;
            float4 w = make_float4(0.f, 0.f, 0.f, 0.f);
            if (gn < N) w = *(const float4*)(B + (size_t)(k0 + kb) * N + gn);
            Bs[kb][n + 0] = w.x; Bs[kb][n + 1] = w.y; Bs[kb][n + 2] = w.z; Bs[kb][n + 3] = w.w;
        }
        __syncthreads();
#pragma unroll
        for (int k = 0; k < 16; k++) {
            float a[8], b[8];
#pragma unroll
            for (int i = 0; i < 8; i++) a[i] = As[k][ty * 8 + i];
#pragma unroll
            for (int j = 0; j < 8; j++) b[j] = Bs[k][tx * 8 + j];
#pragma unroll
            for (int i = 0; i < 8; i++)
#pragma unroll
                for (int j = 0; j < 8; j++) acc[i][j] += a[i] * b[j];
        }
        __syncthreads();
    }
#pragma unroll
    for (int i = 0; i < 8; i++) {
        int r = rowBase + ty * 8 + i;
        if (r >= M) continue;
#pragma unroll
        for (int j = 0; j < 8; j++) {
            int c = colBase + tx * 8 + j;
            if (c >= N) continue;
            float v = acc[i][j];
            if (epi >= 1) v += bias[c];
            if (epi == 2) v = fmaxf(v, 0.f);
            C[(size_t)r * N + c] = v;
        }
    }
}

// ---------------- attention projections: al[n,h]=<h[n,h,:],a_src[h,:]>, ar likewise ----------------
template <int C, int HC>
__global__ void attn_proj(const float* __restrict__ h, const float* __restrict__ as_,
                          const float* __restrict__ ad_)
{
    int n = blockIdx.x;
    int head = threadIdx.x >> 5, lane = threadIdx.x & 31;
    const float* hp = h + (size_t)n * HC + head * C;
    const float* sp = as_ + head * C;
    const float* dp = ad_ + head * C;
    float ss = 0.f, sd = 0.f;
#pragma unroll
    for (int c = lane; c < C; c += 32) {
        float v = hp[c];
        ss += v * sp[c];
        sd += v * dp[c];
    }
#pragma unroll
    for (int o = 16; o; o >>= 1) {
        ss += __shfl_xor_sync(0xffffffffu, ss, o);
        sd += __shfl_xor_sync(0xffffffffu, sd, o);
    }
    if (lane == 0) { g_al[n * 4 + head] = ss; g_ar[n * 4 + head] = sd; }
}

__global__ void init_att()
{
    int t = blockIdx.x * blockDim.x + threadIdx.x;
    if (t < NN * 4) { g_m[t] = 0x007FFFFFu; g_den[t] = 0.f; }  // enc(-inf), 0
}

__global__ void zerof(float* __restrict__ p, int n)
{
    int t = blockIdx.x * blockDim.x + threadIdx.x;
    if (t < n) p[t] = 0.f;
}

// ---------------- edge phase A: logits + segment max (order-independent atomicMax) ----------------
__global__ void edge_logits(const int* __restrict__ src, const int* __restrict__ dst, int E)
{
    int i = blockIdx.x * blockDim.x + threadIdx.x;
    if (i >= E + NN) return;
    int s, d;
    if (i < E) { s = src[i]; d = dst[i]; } else { s = d = i - E; }
    float4 a = *(const float4*)&g_al[s * 4];
    float4 b = *(const float4*)&g_ar[d * 4];
    float e0 = a.x + b.x; e0 = e0 >= 0.f ? e0 : 0.2f * e0;
    float e1 = a.y + b.y; e1 = e1 >= 0.f ? e1 : 0.2f * e1;
    float e2 = a.z + b.z; e2 = e2 >= 0.f ? e2 : 0.2f * e2;
    float e3 = a.w + b.w; e3 = e3 >= 0.f ? e3 : 0.2f * e3;
    *(float4*)&g_e[i * 4] = make_float4(e0, e1, e2, e3);
    atomicMax(&g_m[d * 4 + 0], encf(e0));
    atomicMax(&g_m[d * 4 + 1], encf(e1));
    atomicMax(&g_m[d * 4 + 2], encf(e2));
    atomicMax(&g_m[d * 4 + 3], encf(e3));
}

// ---------------- edge phase B: exp(e - max) + denominator ----------------
__global__ void edge_exp(const int* __restrict__ dst, int E)
{
    int i = blockIdx.x * blockDim.x + threadIdx.x;
    if (i >= E + NN) return;
    int d = (i < E) ? dst[i] : (i - E);
    float4 e = *(const float4*)&g_e[i * 4];
    float x0 = expf(e.x - decf(g_m[d * 4 + 0]));
    float x1 = expf(e.y - decf(g_m[d * 4 + 1]));
    float x2 = expf(e.z - decf(g_m[d * 4 + 2]));
    float x3 = expf(e.w - decf(g_m[d * 4 + 3]));
    *(float4*)&g_e[i * 4] = make_float4(x0, x1, x2, x3);
    atomicAdd(&g_den[d * 4 + 0], x0);
    atomicAdd(&g_den[d * 4 + 1], x1);
    atomicAdd(&g_den[d * 4 + 2], x2);
    atomicAdd(&g_den[d * 4 + 3], x3);
}

__global__ void make_coef()
{
    int t = blockIdx.x * blockDim.x + threadIdx.x;
    if (t < NN * 4) g_den[t] = 1.0f / (4.0f * g_den[t]);  // folds softmax denom + head mean
}

// ---------------- edge phase C: out[dst,c] += sum_h alpha_h/H * h[src,h,c]  (warp per edge) ----------------
template <int C, int HC>
__global__ void edge_aggr(const int* __restrict__ src, const int* __restrict__ dst,
                          const float* __restrict__ h, float* __restrict__ out, int E)
{
    int w = (blockIdx.x * blockDim.x + threadIdx.x) >> 5;
    int lane = threadIdx.x & 31;
    if (w >= E + NN) return;
    int s, d;
    if (w < E) { s = src[w]; d = dst[w]; } else { s = d = w - E; }
    float4 ex = *(const float4*)&g_e[w * 4];
    float4 cf = *(const float4*)&g_den[d * 4];
    float w0 = ex.x * cf.x, w1 = ex.y * cf.y, w2 = ex.z * cf.z, w3 = ex.w * cf.w;
    const float* hs = h + (size_t)s * HC;
    float* od = out + (size_t)d * C;
#pragma unroll
    for (int c = lane; c < C; c += 32) {
        float v = w0 * hs[c] + w1 * hs[C + c] + w2 * hs[2 * C + c] + w3 * hs[3 * C + c];
        atomicAdd(&od[c], v);
    }
}

__global__ void bias_act(float* __restrict__ out, const float* __restrict__ bias,
                         int total, int C, int relu)
{
    int t = blockIdx.x * blockDim.x + threadIdx.x;
    if (t >= total) return;
    float v = out[t] + bias[t % C];
    out[t] = relu ? fmaxf(v, 0.f) : v;
}

// ---------------- reparameterize ----------------
// eps = jax.random.normal(key(1), (10000,64)), threefry2x32, partitionable path
// (modern default): per element i, u64 counter split (hi=ctr>>32 -> x0 lane,
// lo=ctr&0xffffffff -> x1 lane); for 32-bit width the two output lanes are
// XOR-FOLDED: bits[i] = x0_final ^ x1_final.
__device__ __forceinline__ unsigned rotl32(unsigned x, int d) { return (x << d) | (x >> (32 - d)); }

__device__ __forceinline__ float bits_to_normal(unsigned bits) {
    float f = __uint_as_float((bits >> 9) | 0x3f800000u) - 1.0f;   // [0,1)
    const float lo = -0.99999994f;                                  // nextafter(-1,0)
    float u = fmaxf(lo, f * (1.0f - lo) + lo);
    return 1.41421356237f * erfinvf(u);
}

__global__ void reparam(const float* __restrict__ mu, const float* __restrict__ lv,
                        float* __restrict__ z, int n)
{
    int i = blockIdx.x * blockDim.x + threadIdx.x;
    if (i >= n) return;
    // key(1) -> (ks0,ks1) = (0,1); ks2 = 0x1BD11BDA ^ ks0 ^ ks1
    const unsigned ks0 = 0u, ks1 = 1u, ks2 = 0x1BD11BDBu;
    unsigned x0 = 0u + ks0;               // hi 32 bits of u64 counter = 0
    unsigned x1 = (unsigned)i + ks1;      // lo 32 bits of u64 counter = i
#define TFR(r) { x0 += x1; x1 = rotl32(x1, r); x1 ^= x0; }
    TFR(13) TFR(15) TFR(26) TFR(6)
    x0 += ks1; x1 += ks2 + 1u;
    TFR(17) TFR(29) TFR(16) TFR(24)
    x0 += ks2; x1 += ks0 + 2u;
    TFR(13) TFR(15) TFR(26) TFR(6)
    x0 += ks0; x1 += ks1 + 3u;
    TFR(17) TFR(29) TFR(16) TFR(24)
    x0 += ks1; x1 += ks2 + 4u;
    TFR(13) TFR(15) TFR(26) TFR(6)
    x0 += ks2; x1 += ks0 + 5u;
#undef TFR
    float eps = bits_to_normal(x0 ^ x1);  // XOR fold of both output lanes
    z[i] = mu[i] + eps * expf(0.5f * lv[i]);
}

// ---------------- pairwise distance ----------------
__global__ void rownorm(const float* __restrict__ r)
{
    int row = (blockIdx.x * blockDim.x + threadIdx.x) >> 5;
    int lane = threadIdx.x & 31;
    if (row >= NN) return;
    float s = 0.f;
#pragma unroll
    for (int c = lane; c < 128; c += 32) {
        float v = r[(size_t)row * 128 + c];
        s += v * v;
    }
#pragma unroll
    for (int o = 16; o; o >>= 1) s += __shfl_xor_sync(0xffffffffu, s, o);
    if (lane == 0) g_sq[row] = s;
}

__global__ void pd_kernel(const float* __restrict__ R, float* __restrict__ P)
{
    __shared__ float As[16][128];
    __shared__ float Bs[16][128];
    const int tid = threadIdx.x;
    const int tx = tid & 15, ty = tid >> 4;
    const int rb = blockIdx.y * 128, cb = blockIdx.x * 128;
    float acc[8][8];
#pragma unroll
    for (int i = 0; i < 8; i++)
#pragma unroll
        for (int j = 0; j < 8; j++) acc[i][j] = 0.f;

    for (int k0 = 0; k0 < 128; k0 += 16) {
#pragma unroll
        for (int l = 0; l < 2; l++) {
            int i = tid + l * 256;
            int m = i >> 2, kk = (i & 3) << 2;
            int gr = rb + m;
            float4 v = make_float4(0.f, 0.f, 0.f, 0.f);
            if (gr < NN) v = *(const float4*)(R + (size_t)gr * 128 + k0 + kk);
            As[kk + 0][m] = v.x; As[kk + 1][m] = v.y; As[kk + 2][m] = v.z; As[kk + 3][m] = v.w;
            int gc = cb + m;
            float4 w = make_float4(0.f, 0.f, 0.f, 0.f);
            if (gc < NN) w = *(const float4*)(R + (size_t)gc * 128 + k0 + kk);
            Bs[kk + 0][m] = w.x; Bs[kk + 1][m] = w.y; Bs[kk + 2][m] = w.z; Bs[kk + 3][m] = w.w;
        }
        __syncthreads();
#pragma unroll
        for (int k = 0; k < 16; k++) {
            float a[8], b[8];
#pragma unroll
            for (int i = 0; i < 8; i++) a[i] = As[k][ty * 8 + i];
#pragma unroll
            for (int j = 0; j < 8; j++) b[j] = Bs[k][tx * 8 + j];
#pragma unroll
            for (int i = 0; i < 8; i++)
#pragma unroll
                for (int j = 0; j < 8; j++) acc[i][j] += a[i] * b[j];
        }
        __syncthreads();
    }
#pragma unroll
    for (int i = 0; i < 8; i++) {
        int r = rb + ty * 8 + i;
        if (r >= NN) continue;
#pragma unroll
        for (int j = 0; j < 8; j++) {
            int c = cb + tx * 8 + j;
            if (c >= NN) continue;
            float v = g_sq[r] + g_sq[c] - 2.0f * acc[i][j];
            P[(size_t)r * NN + c] = sqrtf(fmaxf(v, 1e-12f));
        }
    }
}

// ---------------- launch ----------------
static inline int divup(int a, int b) { return (a + b - 1) / b; }

extern "C" void kernel_launch(void* const* d_in, const int* in_sizes, int n_in,
                              void* d_out, int out_size)
{
    const float* x   = (const float*)d_in[0];
    const int*   ei  = (const int*)d_in[1];
    const int E = in_sizes[1] / 2;
    const float* W1  = (const float*)d_in[2];
    const float* a1s = (const float*)d_in[3];
    const float* a1d = (const float*)d_in[4];
    const float* b1  = (const float*)d_in[5];
    const float* W2  = (const float*)d_in[6];
    const float* a2s = (const float*)d_in[7];
    const float* a2d = (const float*)d_in[8];
    const float* b2  = (const float*)d_in[9];
    const float* Wmu = (const float*)d_in[10];
    const float* bmu = (const float*)d_in[11];
    const float* Wlv = (const float*)d_in[12];
    const float* blv = (const float*)d_in[13];
    const float* Wd1 = (const float*)d_in[14];
    const float* bd1 = (const float*)d_in[15];
    const float* Wd2 = (const float*)d_in[16];
    const float* bd2 = (const float*)d_in[17];
    const float* W3  = (const float*)d_in[18];
    const float* a3s = (const float*)d_in[19];
    const float* a3d = (const float*)d_in[20];
    const float* b3  = (const float*)d_in[21];

    float* out     = (float*)d_out;
    float* d_recon = out;                               // [NN,128]
    float* d_mu    = out + (size_t)NN * 128;            // [NN,64]
    float* d_lv    = d_mu + (size_t)NN * 64;            // [NN,64]
    float* d_pd    = d_lv + (size_t)NN * 64;            // [NN,NN]

    float *hbuf, *out1, *out2, *zb, *d1b, *d2b;
    cudaGetSymbolAddress((void**)&hbuf, g_hbuf);
    cudaGetSymbolAddress((void**)&out1, g_out1);
    cudaGetSymbolAddress((void**)&out2, g_out2);
    cudaGetSymbolAddress((void**)&zb,   g_zb);
    cudaGetSymbolAddress((void**)&d1b,  g_d1b);
    cudaGetSymbolAddress((void**)&d2b,  g_d2b);

    const int* srcp = ei;
    const int* dstp = ei + E;
    const int ET = E + NN;
    const int EB = divup(ET, 256);
    const int AB = divup(ET * 32, 256);

    // ----- encoder conv1: Fin=128 -> H*256 -----
    sgemm128<<<dim3(8, 79), 256>>>(x, W1, nullptr, hbuf, NN, 1024, 128, 0);
    attn_proj<256, 1024><<<NN, 128>>>(hbuf, a1s, a1d);
    init_att<<<divup(NN * 4, 256), 256>>>();
    zerof<<<divup(NN * 256, 256), 256>>>(out1, NN * 256);
    edge_logits<<<EB, 256>>>(srcp, dstp, E);
    edge_exp<<<EB, 256>>>(dstp, E);
    make_coef<<<divup(NN * 4, 256), 256>>>();
    edge_aggr<256, 1024><<<AB, 256>>>(srcp, dstp, hbuf, out1, E);
    bias_act<<<divup(NN * 256, 256), 256>>>(out1, b1, NN * 256, 256, 1);

    // ----- encoder conv2: 256 -> H*128 -----
    sgemm128<<<dim3(4, 79), 256>>>(out1, W2, nullptr, hbuf, NN, 512, 256, 0);
    attn_proj<128, 512><<<NN, 128>>>(hbuf, a2s, a2d);
    init_att<<<divup(NN * 4, 256), 256>>>();
    zerof<<<divup(NN * 128, 256), 256>>>(out2, NN * 128);
    edge_logits<<<EB, 256>>>(srcp, dstp, E);
    edge_exp<<<EB, 256>>>(dstp, E);
    make_coef<<<divup(NN * 4, 256), 256>>>();
    edge_aggr<128, 512><<<AB, 256>>>(srcp, dstp, hbuf, out2, E);
    bias_act<<<divup(NN * 128, 256), 256>>>(out2, b2, NN * 128, 128, 1);

    // ----- mu / logvar heads -----
    sgemm128<<<dim3(1, 79), 256>>>(out2, Wmu, bmu, d_mu, NN, 64, 128, 1);
    sgemm128<<<dim3(1, 79), 256>>>(out2, Wlv, blv, d_lv, NN, 64, 128, 1);

    // ----- reparameterize (partitionable threefry, XOR-folded lanes) -----
    reparam<<<divup(NN * 64, 256), 256>>>(d_mu, d_lv, zb, NN * 64);

    // ----- decoder dense -----
    sgemm128<<<dim3(1, 79), 256>>>(zb,  Wd1, bd1, d1b, NN, 128, 64, 2);
    sgemm128<<<dim3(2, 79), 256>>>(d1b, Wd2, bd2, d2b, NN, 256, 128, 2);

    // ----- decoder conv3: 256 -> H*128 (no relu) -----
    sgemm128<<<dim3(4, 79), 256>>>(d2b, W3, nullptr, hbuf, NN, 512, 256, 0);
    attn_proj<128, 512><<<NN, 128>>>(hbuf, a3s, a3d);
    init_att<<<divup(NN * 4, 256), 256>>>();
    zerof<<<divup(NN * 128, 256), 256>>>(d_recon, NN * 128);
    edge_logits<<<EB, 256>>>(srcp, dstp, E);
    edge_exp<<<EB, 256>>>(dstp, E);
    make_coef<<<divup(NN * 4, 256), 256>>>();
    edge_aggr<128, 512><<<AB, 256>>>(srcp, dstp, hbuf, d_recon, E);
    bias_act<<<divup(NN * 128, 256), 256>>>(d_recon, b3, NN * 128, 128, 0);

    // ----- pairwise distances -----
    rownorm<<<divup(NN * 32, 256), 256>>>(d_recon);
    pd_kernel<<<dim3(79, 79), 256>>>(d_recon, d_pd);
}

// round 10
// speedup vs baseline: 1.1482x; 1.1482x over previous
#include <cuda_runtime.h>
#include <math.h>

#define NN 10000
#define EMAX 320000
#define ETMAX (EMAX + NN)

// ---------------- scratch (device globals; no allocation allowed) ----------------
__device__ float g_hbuf[NN * 1024];   // h of current conv; later carved for pd hi/lo
__device__ float g_out1[NN * 256];
__device__ float g_out2[NN * 128];
__device__ float g_zb  [NN * 64];
__device__ float g_d1b [NN * 128];
__device__ float g_d2b [NN * 256];
__device__ float g_al  [NN * 4];
__device__ float g_ar  [NN * 4];
__device__ float g_sq  [NN];
__device__ int   g_cnt [NN];          // degree counts -> scatter cursor
__device__ int   g_off [NN + 1];      // CSR offsets
__device__ int   g_perm[ETMAX];       // edge ids grouped by dst

// ---------------- generic 128x128 SGEMM (NN layout), epi: 0=none,1=+bias,2=+bias,relu ----------------
__global__ void sgemm128(const float* __restrict__ A, const float* __restrict__ B,
                         const float* __restrict__ bias, float* __restrict__ C,
                         int M, int N, int K, int epi)
{
    __shared__ float As[16][128];
    __shared__ float Bs[16][128];
    const int tid = threadIdx.x;
    const int tx = tid & 15, ty = tid >> 4;
    const int rowBase = blockIdx.y * 128, colBase = blockIdx.x * 128;
    float acc[8][8];
#pragma unroll
    for (int i = 0; i < 8; i++)
#pragma unroll
        for (int j = 0; j < 8; j++) acc[i][j] = 0.f;

    for (int k0 = 0; k0 < K; k0 += 16) {
#pragma unroll
        for (int l = 0; l < 2; l++) {
            int i  = tid + l * 256;
            int m  = i >> 2, kk = (i & 3) << 2;
            int gm = rowBase + m;
            float4 v = make_float4(0.f, 0.f, 0.f, 0.f);
            if (gm < M) v = *(const float4*)(A + (size_t)gm * K + k0 + kk);
            As[kk + 0][m] = v.x; As[kk + 1][m] = v.y; As[kk + 2][m] = v.z; As[kk + 3][m] = v.w;
            int kb = i >> 5, n = (i & 31) << 2;
            int gn = colBase + n;
            float4 w = make_float4(0.f, 0.f, 0.f, 0.f);
            if (gn < N) w = *(const float4*)(B + (size_t)(k0 + kb) * N + gn);
            Bs[kb][n + 0] = w.x; Bs[kb][n + 1] = w.y; Bs[kb][n + 2] = w.z; Bs[kb][n + 3] = w.w;
        }
        __syncthreads();
#pragma unroll
        for (int k = 0; k < 16; k++) {
            float a[8], b[8];
#pragma unroll
            for (int i = 0; i < 8; i++) a[i] = As[k][ty * 8 + i];
#pragma unroll
            for (int j = 0; j < 8; j++) b[j] = Bs[k][tx * 8 + j];
#pragma unroll
            for (int i = 0; i < 8; i++)
#pragma unroll
                for (int j = 0; j < 8; j++) acc[i][j] += a[i] * b[j];
        }
        __syncthreads();
    }
#pragma unroll
    for (int i = 0; i < 8; i++) {
        int r = rowBase + ty * 8 + i;
        if (r >= M) continue;
#pragma unroll
        for (int j = 0; j < 8; j++) {
            int c = colBase + tx * 8 + j;
            if (c >= N) continue;
            float v = acc[i][j];
            if (epi >= 1) v += bias[c];
            if (epi == 2) v = fmaxf(v, 0.f);
            C[(size_t)r * N + c] = v;
        }
    }
}

// ---------------- attention projections ----------------
template <int C, int HC>
__global__ void attn_proj(const float* __restrict__ h, const float* __restrict__ as_,
                          const float* __restrict__ ad_)
{
    int n = blockIdx.x;
    int head = threadIdx.x >> 5, lane = threadIdx.x & 31;
    const float* hp = h + (size_t)n * HC + head * C;
    const float* sp = as_ + head * C;
    const float* dp = ad_ + head * C;
    float ss = 0.f, sd = 0.f;
#pragma unroll
    for (int c = lane; c < C; c += 32) {
        float v = hp[c];
        ss += v * sp[c];
        sd += v * dp[c];
    }
#pragma unroll
    for (int o = 16; o; o >>= 1) {
        ss += __shfl_xor_sync(0xffffffffu, ss, o);
        sd += __shfl_xor_sync(0xffffffffu, sd, o);
    }
    if (lane == 0) { g_al[n * 4 + head] = ss; g_ar[n * 4 + head] = sd; }
}

// ---------------- CSR build ----------------
__global__ void zero_cnt()
{
    int t = blockIdx.x * blockDim.x + threadIdx.x;
    if (t < NN) g_cnt[t] = 0;
}

__global__ void count_k(const int* __restrict__ dst, int E)
{
    int i = blockIdx.x * blockDim.x + threadIdx.x;
    if (i >= E + NN) return;
    int d = (i < E) ? dst[i] : (i - E);
    atomicAdd(&g_cnt[d], 1);
}

__global__ void scan_k()
{
    __shared__ int s[1024];
    __shared__ int carry_s;
    int tid = threadIdx.x;
    if (tid == 0) carry_s = 0;
    __syncthreads();
    for (int base = 0; base < NN; base += 1024) {
        int i = base + tid;
        int v = (i < NN) ? g_cnt[i] : 0;
        s[tid] = v;
        __syncthreads();
#pragma unroll
        for (int o = 1; o < 1024; o <<= 1) {
            int t = (tid >= o) ? s[tid - o] : 0;
            __syncthreads();
            s[tid] += t;
            __syncthreads();
        }
        int carry = carry_s;
        int excl = carry + s[tid] - v;
        if (i < NN) { g_off[i] = excl; g_cnt[i] = excl; }   // cnt becomes cursor
        int total = s[1023];
        __syncthreads();
        if (tid == 0) carry_s = carry + total;
        __syncthreads();
    }
    if (tid == 0) g_off[NN] = carry_s;
}

__global__ void scatter_k(const int* __restrict__ dst, int E)
{
    int i = blockIdx.x * blockDim.x + threadIdx.x;
    if (i >= E + NN) return;
    int d = (i < E) ? dst[i] : (i - E);
    int pos = atomicAdd(&g_cnt[d], 1);
    g_perm[pos] = i;
}

// ---------------- fused GAT aggregation: block per dst node ----------------
// out[n,c] = relu?( sum_h (1/(4*den_h)) * sum_e ex_{e,h} * h[src_e, h*C+c] + bias[c] )
template <int C, int HC, int RELU>
__global__ void gat_agg(const int* __restrict__ src, int E,
                        const float* __restrict__ h,
                        const float* __restrict__ bias,
                        float* __restrict__ out)
{
    constexpr int ACC = C / 128;
    __shared__ int    sm_s[128];
    __shared__ float4 sm_w[128];
    __shared__ float4 sred[4];

    int n = blockIdx.x;
    int tid = threadIdx.x;
    int wid = tid >> 5, lane = tid & 31;
    int off = g_off[n];
    int deg = g_off[n + 1] - off;

    float4 arn = *(const float4*)&g_ar[n * 4];

    // ---- pass 1: per-head max over incoming edges
    float4 mx = make_float4(-1e30f, -1e30f, -1e30f, -1e30f);
    for (int j = tid; j < deg; j += 128) {
        int e = g_perm[off + j];
        int s = (e < E) ? src[e] : (e - E);
        float4 a = *(const float4*)&g_al[s * 4];
        float l0 = a.x + arn.x; l0 = l0 >= 0.f ? l0 : 0.2f * l0;
        float l1 = a.y + arn.y; l1 = l1 >= 0.f ? l1 : 0.2f * l1;
        float l2 = a.z + arn.z; l2 = l2 >= 0.f ? l2 : 0.2f * l2;
        float l3 = a.w + arn.w; l3 = l3 >= 0.f ? l3 : 0.2f * l3;
        mx.x = fmaxf(mx.x, l0); mx.y = fmaxf(mx.y, l1);
        mx.z = fmaxf(mx.z, l2); mx.w = fmaxf(mx.w, l3);
    }
#pragma unroll
    for (int o = 16; o; o >>= 1) {
        mx.x = fmaxf(mx.x, __shfl_xor_sync(0xffffffffu, mx.x, o));
        mx.y = fmaxf(mx.y, __shfl_xor_sync(0xffffffffu, mx.y, o));
        mx.z = fmaxf(mx.z, __shfl_xor_sync(0xffffffffu, mx.z, o));
        mx.w = fmaxf(mx.w, __shfl_xor_sync(0xffffffffu, mx.w, o));
    }
    if (lane == 0) sred[wid] = mx;
    __syncthreads();
    if (tid == 0) {
        float4 a = sred[0];
#pragma unroll
        for (int w = 1; w < 4; w++) {
            float4 b = sred[w];
            a.x = fmaxf(a.x, b.x); a.y = fmaxf(a.y, b.y);
            a.z = fmaxf(a.z, b.z); a.w = fmaxf(a.w, b.w);
        }
        sred[0] = a;
    }
    __syncthreads();
    mx = sred[0];
    __syncthreads();

    // ---- pass 2: exp + den + unnormalized gather
    float acc0[ACC], acc1[ACC], acc2[ACC], acc3[ACC];
#pragma unroll
    for (int q = 0; q < ACC; q++) { acc0[q] = acc1[q] = acc2[q] = acc3[q] = 0.f; }
    float4 den = make_float4(0.f, 0.f, 0.f, 0.f);

    for (int base = 0; base < deg; base += 128) {
        int cnt = min(128, deg - base);
        int j = base + tid;
        if (j < deg) {
            int e = g_perm[off + j];
            int s = (e < E) ? src[e] : (e - E);
            float4 a = *(const float4*)&g_al[s * 4];
            float l0 = a.x + arn.x; l0 = l0 >= 0.f ? l0 : 0.2f * l0;
            float l1 = a.y + arn.y; l1 = l1 >= 0.f ? l1 : 0.2f * l1;
            float l2 = a.z + arn.z; l2 = l2 >= 0.f ? l2 : 0.2f * l2;
            float l3 = a.w + arn.w; l3 = l3 >= 0.f ? l3 : 0.2f * l3;
            float4 ex = make_float4(expf(l0 - mx.x), expf(l1 - mx.y),
                                    expf(l2 - mx.z), expf(l3 - mx.w));
            den.x += ex.x; den.y += ex.y; den.z += ex.z; den.w += ex.w;
            sm_s[tid] = s;
            sm_w[tid] = ex;
        }
        __syncthreads();
        for (int j2 = 0; j2 < cnt; j2++) {
            int s = sm_s[j2];
            float4 w = sm_w[j2];
            const float* hs = h + (size_t)s * HC;
#pragma unroll
            for (int q = 0; q < ACC; q++) {
                int c = tid + q * 128;
                acc0[q] += w.x * hs[c];
                acc1[q] += w.y * hs[C + c];
                acc2[q] += w.z * hs[2 * C + c];
                acc3[q] += w.w * hs[3 * C + c];
            }
        }
        __syncthreads();
    }

    // reduce den across block
#pragma unroll
    for (int o = 16; o; o >>= 1) {
        den.x += __shfl_xor_sync(0xffffffffu, den.x, o);
        den.y += __shfl_xor_sync(0xffffffffu, den.y, o);
        den.z += __shfl_xor_sync(0xffffffffu, den.z, o);
        den.w += __shfl_xor_sync(0xffffffffu, den.w, o);
    }
    if (lane == 0) sred[wid] = den;
    __syncthreads();
    if (tid == 0) {
        float4 a = sred[0];
#pragma unroll
        for (int w = 1; w < 4; w++) {
            float4 b = sred[w];
            a.x += b.x; a.y += b.y; a.z += b.z; a.w += b.w;
        }
        sred[0] = a;
    }
    __syncthreads();
    den = sred[0];

    float i0 = 1.0f / (4.0f * den.x);
    float i1 = 1.0f / (4.0f * den.y);
    float i2 = 1.0f / (4.0f * den.z);
    float i3 = 1.0f / (4.0f * den.w);
#pragma unroll
    for (int q = 0; q < ACC; q++) {
        int c = tid + q * 128;
        float v = acc0[q] * i0 + acc1[q] * i1 + acc2[q] * i2 + acc3[q] * i3 + bias[c];
        if (RELU) v = fmaxf(v, 0.f);
        out[(size_t)n * C + c] = v;
    }
}

// ---------------- reparameterize: partitionable threefry, XOR-folded lanes (R7-verified) ----------------
__device__ __forceinline__ unsigned rotl32(unsigned x, int d) { return (x << d) | (x >> (32 - d)); }

__device__ __forceinline__ float bits_to_normal(unsigned bits) {
    float f = __uint_as_float((bits >> 9) | 0x3f800000u) - 1.0f;   // [0,1)
    const float lo = -0.99999994f;
    float u = fmaxf(lo, f * (1.0f - lo) + lo);
    return 1.41421356237f * erfinvf(u);
}

__global__ void reparam(const float* __restrict__ mu, const float* __restrict__ lv,
                        float* __restrict__ z, int n)
{
    int i = blockIdx.x * blockDim.x + threadIdx.x;
    if (i >= n) return;
    const unsigned ks0 = 0u, ks1 = 1u, ks2 = 0x1BD11BDBu;
    unsigned x0 = 0u + ks0;
    unsigned x1 = (unsigned)i + ks1;
#define TFR(r) { x0 += x1; x1 = rotl32(x1, r); x1 ^= x0; }
    TFR(13) TFR(15) TFR(26) TFR(6)
    x0 += ks1; x1 += ks2 + 1u;
    TFR(17) TFR(29) TFR(16) TFR(24)
    x0 += ks2; x1 += ks0 + 2u;
    TFR(13) TFR(15) TFR(26) TFR(6)
    x0 += ks0; x1 += ks1 + 3u;
    TFR(17) TFR(29) TFR(16) TFR(24)
    x0 += ks1; x1 += ks2 + 4u;
    TFR(13) TFR(15) TFR(26) TFR(6)
    x0 += ks2; x1 += ks0 + 5u;
#undef TFR
    float eps = bits_to_normal(x0 ^ x1);
    z[i] = mu[i] + eps * expf(0.5f * lv[i]);
}

// ---------------- pd prep: row norms + tf32 hi/lo split ----------------
__global__ void rownorm_split(const float* __restrict__ r,
                              float* __restrict__ phi, float* __restrict__ plo)
{
    int row = (blockIdx.x * blockDim.x + threadIdx.x) >> 5;
    int lane = threadIdx.x & 31;
    if (row >= NN) return;
    float s = 0.f;
#pragma unroll
    for (int c = lane; c < 128; c += 32) {
        float v = r[(size_t)row * 128 + c];
        s += v * v;
        float hi = __uint_as_float(__float_as_uint(v) & 0xFFFFE000u);
        float lo = v - hi;
        lo = __uint_as_float(__float_as_uint(lo) & 0xFFFFE000u);
        phi[(size_t)row * 128 + c] = hi;
        plo[(size_t)row * 128 + c] = lo;
    }
#pragma unroll
    for (int o = 16; o; o >>= 1) s += __shfl_xor_sync(0xffffffffu, s, o);
    if (lane == 0) g_sq[row] = s;
}

// ---------------- pd via tf32 split mma (hi*hi + hi*lo + lo*hi) ----------------
#define PDS 40   // smem row stride (floats): 16 k * 2 (hi,lo) + 8 pad

__device__ __forceinline__ void mma8(float* d, unsigned a0, unsigned a1, unsigned a2, unsigned a3,
                                     unsigned b0, unsigned b1)
{
    asm("mma.sync.aligned.m16n8k8.row.col.f32.tf32.tf32.f32 "
        "{%0,%1,%2,%3}, {%4,%5,%6,%7}, {%8,%9}, {%0,%1,%2,%3};\n"
        : "+f"(d[0]), "+f"(d[1]), "+f"(d[2]), "+f"(d[3])
        : "r"(a0), "r"(a1), "r"(a2), "r"(a3), "r"(b0), "r"(b1));
}

__global__ void __launch_bounds__(256, 1)
pd_tc(const float* __restrict__ Rhi, const float* __restrict__ Rlo,
      float* __restrict__ P)
{
    __shared__ float As[128 * PDS];
    __shared__ float Bs[128 * PDS];
    const int tid = threadIdx.x;
    const int wid = tid >> 5, lane = tid & 31;
    const int wm = wid & 1, wn = wid >> 1;        // warps 2 (m) x 4 (n)
    const int grp = lane >> 2, tig = lane & 3;
    const int rb = blockIdx.y * 128, cb = blockIdx.x * 128;

    float acc[4][4][4];
#pragma unroll
    for (int mt = 0; mt < 4; mt++)
#pragma unroll
        for (int nt = 0; nt < 4; nt++)
#pragma unroll
            for (int q = 0; q < 4; q++) acc[mt][nt][q] = 0.f;

    for (int kt = 0; kt < 8; kt++) {              // K=128 in tiles of 16
#pragma unroll
        for (int l = 0; l < 2; l++) {
            int idx = tid + l * 256;              // 0..511
            int row = idx >> 2, q = idx & 3;
            int gr = rb + row;
            int gc = cb + row;
            float4 h4 = make_float4(0.f, 0.f, 0.f, 0.f), l4 = h4;
            if (gr < NN) {
                h4 = *(const float4*)&Rhi[(size_t)gr * 128 + kt * 16 + q * 4];
                l4 = *(const float4*)&Rlo[(size_t)gr * 128 + kt * 16 + q * 4];
            }
            float* dp = &As[row * PDS + q * 8];
            dp[0] = h4.x; dp[1] = l4.x; dp[2] = h4.y; dp[3] = l4.y;
            dp[4] = h4.z; dp[5] = l4.z; dp[6] = h4.w; dp[7] = l4.w;
            h4 = make_float4(0.f, 0.f, 0.f, 0.f); l4 = h4;
            if (gc < NN) {
                h4 = *(const float4*)&Rhi[(size_t)gc * 128 + kt * 16 + q * 4];
                l4 = *(const float4*)&Rlo[(size_t)gc * 128 + kt * 16 + q * 4];
            }
            dp = &Bs[row * PDS + q * 8];
            dp[0] = h4.x; dp[1] = l4.x; dp[2] = h4.y; dp[3] = l4.y;
            dp[4] = h4.z; dp[5] = l4.z; dp[6] = h4.w; dp[7] = l4.w;
        }
        __syncthreads();
#pragma unroll
        for (int kc = 0; kc < 16; kc += 8) {
            unsigned ahi[4][4], alo[4][4];
#pragma unroll
            for (int mt = 0; mt < 4; mt++) {
                int r0 = (wm * 64 + mt * 16 + grp) * PDS + (kc + tig) * 2;
                int r1 = r0 + 8 * PDS;
                float2 p0 = *(const float2*)&As[r0];
                float2 p1 = *(const float2*)&As[r1];
                float2 p2 = *(const float2*)&As[r0 + 8];
                float2 p3 = *(const float2*)&As[r1 + 8];
                ahi[mt][0] = __float_as_uint(p0.x); alo[mt][0] = __float_as_uint(p0.y);
                ahi[mt][1] = __float_as_uint(p1.x); alo[mt][1] = __float_as_uint(p1.y);
                ahi[mt][2] = __float_as_uint(p2.x); alo[mt][2] = __float_as_uint(p2.y);
                ahi[mt][3] = __float_as_uint(p3.x); alo[mt][3] = __float_as_uint(p3.y);
            }
            unsigned bhi[4][2], blo[4][2];
#pragma unroll
            for (int nt = 0; nt < 4; nt++) {
                int rn = (wn * 32 + nt * 8 + grp) * PDS + (kc + tig) * 2;
                float2 q0 = *(const float2*)&Bs[rn];
                float2 q1 = *(const float2*)&Bs[rn + 8];
                bhi[nt][0] = __float_as_uint(q0.x); blo[nt][0] = __float_as_uint(q0.y);
                bhi[nt][1] = __float_as_uint(q1.x); blo[nt][1] = __float_as_uint(q1.y);
            }
#pragma unroll
            for (int mt = 0; mt < 4; mt++)
#pragma unroll
                for (int nt = 0; nt < 4; nt++) {
                    mma8(acc[mt][nt], ahi[mt][0], ahi[mt][1], ahi[mt][2], ahi[mt][3],
                         bhi[nt][0], bhi[nt][1]);
                    mma8(acc[mt][nt], ahi[mt][0], ahi[mt][1], ahi[mt][2], ahi[mt][3],
                         blo[nt][0], blo[nt][1]);
                    mma8(acc[mt][nt], alo[mt][0], alo[mt][1], alo[mt][2], alo[mt][3],
                         bhi[nt][0], bhi[nt][1]);
                }
        }
        __syncthreads();
    }

    // epilogue: d = sqrt(max(sq_r + sq_c - 2*dot, 1e-12))
#pragma unroll
    for (int mt = 0; mt < 4; mt++) {
        int r0 = rb + wm * 64 + mt * 16 + grp;
        int r1 = r0 + 8;
        float sq0 = (r0 < NN) ? g_sq[r0] : 0.f;
        float sq1 = (r1 < NN) ? g_sq[r1] : 0.f;
#pragma unroll
        for (int nt = 0; nt < 4; nt++) {
            int c = cb + wn * 32 + nt * 8 + tig * 2;
            if (c + 1 < NN) {
                float sc0 = g_sq[c], sc1 = g_sq[c + 1];
                if (r0 < NN) {
                    float2 v;
                    v.x = sqrtf(fmaxf(sq0 + sc0 - 2.f * acc[mt][nt][0], 1e-12f));
                    v.y = sqrtf(fmaxf(sq0 + sc1 - 2.f * acc[mt][nt][1], 1e-12f));
                    *(float2*)&P[(size_t)r0 * NN + c] = v;
                }
                if (r1 < NN) {
                    float2 v;
                    v.x = sqrtf(fmaxf(sq1 + sc0 - 2.f * acc[mt][nt][2], 1e-12f));
                    v.y = sqrtf(fmaxf(sq1 + sc1 - 2.f * acc[mt][nt][3], 1e-12f));
                    *(float2*)&P[(size_t)r1 * NN + c] = v;
                }
            } else if (c < NN) {
                float sc0 = g_sq[c];
                if (r0 < NN) P[(size_t)r0 * NN + c] =
                    sqrtf(fmaxf(sq0 + sc0 - 2.f * acc[mt][nt][0], 1e-12f));
                if (r1 < NN) P[(size_t)r1 * NN + c] =
                    sqrtf(fmaxf(sq1 + sc0 - 2.f * acc[mt][nt][2], 1e-12f));
            }
        }
    }
}

// ---------------- launch ----------------
static inline int divup(int a, int b) { return (a + b - 1) / b; }

extern "C" void kernel_launch(void* const* d_in, const int* in_sizes, int n_in,
                              void* d_out, int out_size)
{
    const float* x   = (const float*)d_in[0];
    const int*   ei  = (const int*)d_in[1];
    const int E = in_sizes[1] / 2;
    const float* W1  = (const float*)d_in[2];
    const float* a1s = (const float*)d_in[3];
    const float* a1d = (const float*)d_in[4];
    const float* b1  = (const float*)d_in[5];
    const float* W2  = (const float*)d_in[6];
    const float* a2s = (const float*)d_in[7];
    const float* a2d = (const float*)d_in[8];
    const float* b2  = (const float*)d_in[9];
    const float* Wmu = (const float*)d_in[10];
    const float* bmu = (const float*)d_in[11];
    const float* Wlv = (const float*)d_in[12];
    const float* blv = (const float*)d_in[13];
    const float* Wd1 = (const float*)d_in[14];
    const float* bd1 = (const float*)d_in[15];
    const float* Wd2 = (const float*)d_in[16];
    const float* bd2 = (const float*)d_in[17];
    const float* W3  = (const float*)d_in[18];
    const float* a3s = (const float*)d_in[19];
    const float* a3d = (const float*)d_in[20];
    const float* b3  = (const float*)d_in[21];

    float* out     = (float*)d_out;
    float* d_recon = out;                               // [NN,128]
    float* d_mu    = out + (size_t)NN * 128;            // [NN,64]
    float* d_lv    = d_mu + (size_t)NN * 64;            // [NN,64]
    float* d_pd    = d_lv + (size_t)NN * 64;            // [NN,NN]

    float *hbuf, *out1, *out2, *zb, *d1b, *d2b;
    cudaGetSymbolAddress((void**)&hbuf, g_hbuf);
    cudaGetSymbolAddress((void**)&out1, g_out1);
    cudaGetSymbolAddress((void**)&out2, g_out2);
    cudaGetSymbolAddress((void**)&zb,   g_zb);
    cudaGetSymbolAddress((void**)&d1b,  g_d1b);
    cudaGetSymbolAddress((void**)&d2b,  g_d2b);

    const int* srcp = ei;
    const int* dstp = ei + E;
    const int ET = E + NN;
    const int EB = divup(ET, 256);

    // ----- CSR build (edge list grouped by dst; shared by all 3 convs) -----
    zero_cnt<<<divup(NN, 256), 256>>>();
    count_k<<<EB, 256>>>(dstp, E);
    scan_k<<<1, 1024>>>();
    scatter_k<<<EB, 256>>>(dstp, E);

    // ----- encoder conv1: Fin=128 -> H*256 -----
    sgemm128<<<dim3(8, 79), 256>>>(x, W1, nullptr, hbuf, NN, 1024, 128, 0);
    attn_proj<256, 1024><<<NN, 128>>>(hbuf, a1s, a1d);
    gat_agg<256, 1024, 1><<<NN, 128>>>(srcp, E, hbuf, b1, out1);

    // ----- encoder conv2: 256 -> H*128 -----
    sgemm128<<<dim3(4, 79), 256>>>(out1, W2, nullptr, hbuf, NN, 512, 256, 0);
    attn_proj<128, 512><<<NN, 128>>>(hbuf, a2s, a2d);
    gat_agg<128, 512, 1><<<NN, 128>>>(srcp, E, hbuf, b2, out2);

    // ----- mu / logvar heads -----
    sgemm128<<<dim3(1, 79), 256>>>(out2, Wmu, bmu, d_mu, NN, 64, 128, 1);
    sgemm128<<<dim3(1, 79), 256>>>(out2, Wlv, blv, d_lv, NN, 64, 128, 1);

    // ----- reparameterize -----
    reparam<<<divup(NN * 64, 256), 256>>>(d_mu, d_lv, zb, NN * 64);

    // ----- decoder dense -----
    sgemm128<<<dim3(1, 79), 256>>>(zb,  Wd1, bd1, d1b, NN, 128, 64, 2);
    sgemm128<<<dim3(2, 79), 256>>>(d1b, Wd2, bd2, d2b, NN, 256, 128, 2);

    // ----- decoder conv3: 256 -> H*128 (no relu) -----
    sgemm128<<<dim3(4, 79), 256>>>(d2b, W3, nullptr, hbuf, NN, 512, 256, 0);
    attn_proj<128, 512><<<NN, 128>>>(hbuf, a3s, a3d);
    gat_agg<128, 512, 0><<<NN, 128>>>(srcp, E, hbuf, b3, d_recon);

    // ----- pairwise distances (tf32 split tensor path) -----
    float* phi = hbuf;                    // hbuf free after conv3 aggregation
    float* plo = hbuf + (size_t)NN * 128;
    rownorm_split<<<divup(NN * 32, 256), 256>>>(d_recon, phi, plo);
    pd_tc<<<dim3(79, 79), 256>>>(phi, plo, d_pd);
}

// round 13
// speedup vs baseline: 1.3076x; 1.1388x over previous
#include <cuda_runtime.h>
#include <math.h>

#define NN 10000
#define EMAX 320000
#define ETMAX (EMAX + NN)

// ---------------- scratch (device globals; no allocation allowed) ----------------
__device__ __align__(16) float g_hbuf[NN * 1024];
__device__ __align__(16) float g_out1[NN * 256];
__device__ __align__(16) float g_out2[NN * 128];
__device__ __align__(16) float g_zb  [NN * 64];
__device__ __align__(16) float g_d1b [NN * 128];
__device__ __align__(16) float g_d2b [NN * 256];
__device__ __align__(16) float g_al  [NN * 4];
__device__ __align__(16) float g_ar  [NN * 4];
__device__ float g_sq  [NN];
__device__ int   g_cnt [NN];
__device__ int   g_off [NN + 1];
__device__ int   g_perm[ETMAX];

#define PDS 40   // smem row stride (floats): 16 k * 2 (hi,lo) + 8 pad

__device__ __forceinline__ void mma8(float* d, unsigned a0, unsigned a1, unsigned a2, unsigned a3,
                                     unsigned b0, unsigned b1)
{
    asm("mma.sync.aligned.m16n8k8.row.col.f32.tf32.tf32.f32 "
        "{%0,%1,%2,%3}, {%4,%5,%6,%7}, {%8,%9}, {%0,%1,%2,%3};\n"
        : "+f"(d[0]), "+f"(d[1]), "+f"(d[2]), "+f"(d[3])
        : "r"(a0), "r"(a1), "r"(a2), "r"(a3), "r"(b0), "r"(b1));
}

__device__ __forceinline__ void split_tf32(float v, float& hi, float& lo)
{
    hi = __uint_as_float(__float_as_uint(v) & 0xFFFFE000u);
    float l = v - hi;
    lo = __uint_as_float(__float_as_uint(l) & 0xFFFFE000u);
}

// ---------------- split-tf32 tensor-core GEMM: C[M,N] = A[M,K] @ B[K,N] ----------------
// epi: 0=none, 1=+bias, 2=+bias,relu.  K % 16 == 0; N guarded; M guarded.
__global__ void __launch_bounds__(256)
sgemm_tc(const float* __restrict__ A, const float* __restrict__ B,
         const float* __restrict__ bias, float* __restrict__ C,
         int M, int N, int K, int epi)
{
    __shared__ float As[128 * PDS];
    __shared__ float Bs[128 * PDS];
    const int tid = threadIdx.x;
    const int wid = tid >> 5, lane = tid & 31;
    const int wm = wid & 1, wn = wid >> 1;
    const int grp = lane >> 2, tig = lane & 3;
    const int rb = blockIdx.y * 128, cb = blockIdx.x * 128;

    float acc[4][4][4];
#pragma unroll
    for (int mt = 0; mt < 4; mt++)
#pragma unroll
        for (int nt = 0; nt < 4; nt++)
#pragma unroll
            for (int q = 0; q < 4; q++) acc[mt][nt][q] = 0.f;

    for (int k0 = 0; k0 < K; k0 += 16) {
        // A tile 128x16, hi/lo interleaved
#pragma unroll
        for (int l = 0; l < 2; l++) {
            int idx = tid + l * 256;
            int row = idx >> 2, q = idx & 3;
            int gm = rb + row;
            float4 v = make_float4(0.f, 0.f, 0.f, 0.f);
            if (gm < M) v = *(const float4*)(A + (size_t)gm * K + k0 + q * 4);
            float* dp = &As[row * PDS + q * 8];
            split_tf32(v.x, dp[0], dp[1]);
            split_tf32(v.y, dp[2], dp[3]);
            split_tf32(v.z, dp[4], dp[5]);
            split_tf32(v.w, dp[6], dp[7]);
        }
        // B tile 16x128, transposed into [n][k] hi/lo interleaved
#pragma unroll
        for (int l = 0; l < 2; l++) {
            int idx = tid + l * 256;
            int kb = idx & 15, n4 = idx >> 4;       // n4: 0..31
            int gn = cb + n4 * 4;
            float4 w = make_float4(0.f, 0.f, 0.f, 0.f);
            if (gn + 3 < N) w = *(const float4*)(B + (size_t)(k0 + kb) * N + gn);
            else if (gn < N) {
                w.x = B[(size_t)(k0 + kb) * N + gn];
                if (gn + 1 < N) w.y = B[(size_t)(k0 + kb) * N + gn + 1];
                if (gn + 2 < N) w.z = B[(size_t)(k0 + kb) * N + gn + 2];
            }
            float hi, lo;
            split_tf32(w.x, hi, lo);
            Bs[(n4 * 4 + 0) * PDS + kb * 2] = hi; Bs[(n4 * 4 + 0) * PDS + kb * 2 + 1] = lo;
            split_tf32(w.y, hi, lo);
            Bs[(n4 * 4 + 1) * PDS + kb * 2] = hi; Bs[(n4 * 4 + 1) * PDS + kb * 2 + 1] = lo;
            split_tf32(w.z, hi, lo);
            Bs[(n4 * 4 + 2) * PDS + kb * 2] = hi; Bs[(n4 * 4 + 2) * PDS + kb * 2 + 1] = lo;
            split_tf32(w.w, hi, lo);
            Bs[(n4 * 4 + 3) * PDS + kb * 2] = hi; Bs[(n4 * 4 + 3) * PDS + kb * 2 + 1] = lo;
        }
        __syncthreads();
#pragma unroll
        for (int kc = 0; kc < 16; kc += 8) {
            unsigned ahi[4][4], alo[4][4];
#pragma unroll
            for (int mt = 0; mt < 4; mt++) {
                int r0 = (wm * 64 + mt * 16 + grp) * PDS + (kc + tig) * 2;
                int r1 = r0 + 8 * PDS;
                float2 p0 = *(const float2*)&As[r0];
                float2 p1 = *(const float2*)&As[r1];
                float2 p2 = *(const float2*)&As[r0 + 8];
                float2 p3 = *(const float2*)&As[r1 + 8];
                ahi[mt][0] = __float_as_uint(p0.x); alo[mt][0] = __float_as_uint(p0.y);
                ahi[mt][1] = __float_as_uint(p1.x); alo[mt][1] = __float_as_uint(p1.y);
                ahi[mt][2] = __float_as_uint(p2.x); alo[mt][2] = __float_as_uint(p2.y);
                ahi[mt][3] = __float_as_uint(p3.x); alo[mt][3] = __float_as_uint(p3.y);
            }
            unsigned bhi[4][2], blo[4][2];
#pragma unroll
            for (int nt = 0; nt < 4; nt++) {
                int rn = (wn * 32 + nt * 8 + grp) * PDS + (kc + tig) * 2;
                float2 q0 = *(const float2*)&Bs[rn];
                float2 q1 = *(const float2*)&Bs[rn + 8];
                bhi[nt][0] = __float_as_uint(q0.x); blo[nt][0] = __float_as_uint(q0.y);
                bhi[nt][1] = __float_as_uint(q1.x); blo[nt][1] = __float_as_uint(q1.y);
            }
#pragma unroll
            for (int mt = 0; mt < 4; mt++)
#pragma unroll
                for (int nt = 0; nt < 4; nt++) {
                    mma8(acc[mt][nt], ahi[mt][0], ahi[mt][1], ahi[mt][2], ahi[mt][3],
                         bhi[nt][0], bhi[nt][1]);
                    mma8(acc[mt][nt], ahi[mt][0], ahi[mt][1], ahi[mt][2], ahi[mt][3],
                         blo[nt][0], blo[nt][1]);
                    mma8(acc[mt][nt], alo[mt][0], alo[mt][1], alo[mt][2], alo[mt][3],
                         bhi[nt][0], bhi[nt][1]);
                }
        }
        __syncthreads();
    }

#pragma unroll
    for (int mt = 0; mt < 4; mt++) {
        int r0 = rb + wm * 64 + mt * 16 + grp;
        int r1 = r0 + 8;
#pragma unroll
        for (int nt = 0; nt < 4; nt++) {
            int c = cb + wn * 32 + nt * 8 + tig * 2;
            if (c >= N) continue;
            float b0 = 0.f, b1 = 0.f;
            if (epi >= 1) { b0 = bias[c]; b1 = bias[c + 1]; }
            if (r0 < M) {
                float v0 = acc[mt][nt][0] + b0, v1 = acc[mt][nt][1] + b1;
                if (epi == 2) { v0 = fmaxf(v0, 0.f); v1 = fmaxf(v1, 0.f); }
                float2 v = make_float2(v0, v1);
                *(float2*)&C[(size_t)r0 * N + c] = v;
            }
            if (r1 < M) {
                float v0 = acc[mt][nt][2] + b0, v1 = acc[mt][nt][3] + b1;
                if (epi == 2) { v0 = fmaxf(v0, 0.f); v1 = fmaxf(v1, 0.f); }
                float2 v = make_float2(v0, v1);
                *(float2*)&C[(size_t)r1 * N + c] = v;
            }
        }
    }
}

// ---------------- attention projections ----------------
template <int C, int HC>
__global__ void attn_proj(const float* __restrict__ h, const float* __restrict__ as_,
                          const float* __restrict__ ad_)
{
    int n = blockIdx.x;
    int head = threadIdx.x >> 5, lane = threadIdx.x & 31;
    const float* hp = h + (size_t)n * HC + head * C;
    const float* sp = as_ + head * C;
    const float* dp = ad_ + head * C;
    float ss = 0.f, sd = 0.f;
#pragma unroll
    for (int c = lane; c < C; c += 32) {
        float v = hp[c];
        ss += v * sp[c];
        sd += v * dp[c];
    }
#pragma unroll
    for (int o = 16; o; o >>= 1) {
        ss += __shfl_xor_sync(0xffffffffu, ss, o);
        sd += __shfl_xor_sync(0xffffffffu, sd, o);
    }
    if (lane == 0) { g_al[n * 4 + head] = ss; g_ar[n * 4 + head] = sd; }
}

// ---------------- CSR build ----------------
__global__ void zero_cnt()
{
    int t = blockIdx.x * blockDim.x + threadIdx.x;
    if (t < NN) g_cnt[t] = 0;
}

__global__ void count_k(const int* __restrict__ dst, int E)
{
    int i = blockIdx.x * blockDim.x + threadIdx.x;
    if (i >= E + NN) return;
    int d = (i < E) ? dst[i] : (i - E);
    atomicAdd(&g_cnt[d], 1);
}

__global__ void scan_k()   // 1024 threads, single block, single pass
{
    __shared__ int wsum[32];
    const int PER = 10;    // 1024*10 >= NN
    int tid = threadIdx.x;
    int lane = tid & 31, wid = tid >> 5;
    int base = tid * PER;
    int v[PER];
    int s = 0;
#pragma unroll
    for (int q = 0; q < PER; q++) {
        int i = base + q;
        v[q] = (i < NN) ? g_cnt[i] : 0;
        s += v[q];
    }
    int t = s;
#pragma unroll
    for (int o = 1; o < 32; o <<= 1) {
        int u = __shfl_up_sync(0xffffffffu, t, o);
        if (lane >= o) t += u;
    }
    if (lane == 31) wsum[wid] = t;
    __syncthreads();
    if (wid == 0) {
        int w = wsum[lane];
#pragma unroll
        for (int o = 1; o < 32; o <<= 1) {
            int u = __shfl_up_sync(0xffffffffu, w, o);
            if (lane >= o) w += u;
        }
        wsum[lane] = w;
    }
    __syncthreads();
    int excl = t - s + ((wid > 0) ? wsum[wid - 1] : 0);
#pragma unroll
    for (int q = 0; q < PER; q++) {
        int i = base + q;
        if (i < NN) { g_off[i] = excl; g_cnt[i] = excl; }
        excl += v[q];
    }
    if (tid == 1023) g_off[NN] = excl;
}

__global__ void scatter_k(const int* __restrict__ dst, int E)
{
    int i = blockIdx.x * blockDim.x + threadIdx.x;
    if (i >= E + NN) return;
    int d = (i < E) ? dst[i] : (i - E);
    int pos = atomicAdd(&g_cnt[d], 1);
    g_perm[pos] = i;
}

// ---------------- fused GAT aggregation: block per dst node, vectorized gather ----------------
// thread t: head = t>>5, col4-slot = t&31 (+q*32); one LDG.128 per edge per thread.
template <int C, int HC, int RELU>
__global__ void gat_agg(const int* __restrict__ src, int E,
                        const float* __restrict__ h,
                        const float* __restrict__ bias,
                        float* __restrict__ out)
{
    constexpr int ACC = C / 128;
    __shared__ int    sm_s[128];
    __shared__ float4 sm_w[128];      // reused as cross-head combine buffer at the end
    __shared__ float4 sred[4];

    int n = blockIdx.x;
    int tid = threadIdx.x;
    int wid = tid >> 5, lane = tid & 31;
    int head = wid;                   // 4 warps = 4 heads
    int slot = lane;                  // col4 slot within head row
    int off = g_off[n];
    int deg = g_off[n + 1] - off;

    float4 arn = *(const float4*)&g_ar[n * 4];

    // ---- pass 1: per-head max
    float4 mx = make_float4(-1e30f, -1e30f, -1e30f, -1e30f);
    for (int j = tid; j < deg; j += 128) {
        int e = g_perm[off + j];
        int s = (e < E) ? src[e] : (e - E);
        float4 a = *(const float4*)&g_al[s * 4];
        float l0 = a.x + arn.x; l0 = l0 >= 0.f ? l0 : 0.2f * l0;
        float l1 = a.y + arn.y; l1 = l1 >= 0.f ? l1 : 0.2f * l1;
        float l2 = a.z + arn.z; l2 = l2 >= 0.f ? l2 : 0.2f * l2;
        float l3 = a.w + arn.w; l3 = l3 >= 0.f ? l3 : 0.2f * l3;
        mx.x = fmaxf(mx.x, l0); mx.y = fmaxf(mx.y, l1);
        mx.z = fmaxf(mx.z, l2); mx.w = fmaxf(mx.w, l3);
    }
#pragma unroll
    for (int o = 16; o; o >>= 1) {
        mx.x = fmaxf(mx.x, __shfl_xor_sync(0xffffffffu, mx.x, o));
        mx.y = fmaxf(mx.y, __shfl_xor_sync(0xffffffffu, mx.y, o));
        mx.z = fmaxf(mx.z, __shfl_xor_sync(0xffffffffu, mx.z, o));
        mx.w = fmaxf(mx.w, __shfl_xor_sync(0xffffffffu, mx.w, o));
    }
    if (lane == 0) sred[wid] = mx;
    __syncthreads();
    if (tid == 0) {
        float4 a = sred[0];
#pragma unroll
        for (int w = 1; w < 4; w++) {
            float4 b = sred[w];
            a.x = fmaxf(a.x, b.x); a.y = fmaxf(a.y, b.y);
            a.z = fmaxf(a.z, b.z); a.w = fmaxf(a.w, b.w);
        }
        sred[0] = a;
    }
    __syncthreads();
    mx = sred[0];
    __syncthreads();

    // ---- pass 2: exp + den + vectorized unnormalized gather
    float4 acc[ACC];
#pragma unroll
    for (int q = 0; q < ACC; q++) acc[q] = make_float4(0.f, 0.f, 0.f, 0.f);
    float4 den = make_float4(0.f, 0.f, 0.f, 0.f);
    const float* sm_wf = (const float*)sm_w;

    for (int base = 0; base < deg; base += 128) {
        int cnt = min(128, deg - base);
        int j = base + tid;
        if (j < deg) {
            int e = g_perm[off + j];
            int s = (e < E) ? src[e] : (e - E);
            float4 a = *(const float4*)&g_al[s * 4];
            float l0 = a.x + arn.x; l0 = l0 >= 0.f ? l0 : 0.2f * l0;
            float l1 = a.y + arn.y; l1 = l1 >= 0.f ? l1 : 0.2f * l1;
            float l2 = a.z + arn.z; l2 = l2 >= 0.f ? l2 : 0.2f * l2;
            float l3 = a.w + arn.w; l3 = l3 >= 0.f ? l3 : 0.2f * l3;
            float4 ex = make_float4(expf(l0 - mx.x), expf(l1 - mx.y),
                                    expf(l2 - mx.z), expf(l3 - mx.w));
            den.x += ex.x; den.y += ex.y; den.z += ex.z; den.w += ex.w;
            sm_s[tid] = s;
            sm_w[tid] = ex;
        }
        __syncthreads();
#pragma unroll 4
        for (int j2 = 0; j2 < cnt; j2++) {
            int s = sm_s[j2];
            float w = sm_wf[j2 * 4 + head];
            const float4* hs = (const float4*)(h + (size_t)s * HC + head * C);
#pragma unroll
            for (int q = 0; q < ACC; q++) {
                float4 v = hs[slot + q * 32];
                acc[q].x += w * v.x; acc[q].y += w * v.y;
                acc[q].z += w * v.z; acc[q].w += w * v.w;
            }
        }
        __syncthreads();
    }

    // reduce den across block
#pragma unroll
    for (int o = 16; o; o >>= 1) {
        den.x += __shfl_xor_sync(0xffffffffu, den.x, o);
        den.y += __shfl_xor_sync(0xffffffffu, den.y, o);
        den.z += __shfl_xor_sync(0xffffffffu, den.z, o);
        den.w += __shfl_xor_sync(0xffffffffu, den.w, o);
    }
    if (lane == 0) sred[wid] = den;
    __syncthreads();
    if (tid == 0) {
        float4 a = sred[0];
#pragma unroll
        for (int w = 1; w < 4; w++) {
            float4 b = sred[w];
            a.x += b.x; a.y += b.y; a.z += b.z; a.w += b.w;
        }
        sred[0] = a;
    }
    __syncthreads();
    den = sred[0];
    float d4[4];
    *(float4*)d4 = den;
    float mi = 1.0f / (4.0f * d4[head]);     // per-head scale (softmax denom + head mean)

    // cross-head combine via smem (reuse sm_w buffer)
    float4* sm_acc = sm_w;
#pragma unroll
    for (int q = 0; q < ACC; q++) {
        __syncthreads();
        float4 a = acc[q];
        a.x *= mi; a.y *= mi; a.z *= mi; a.w *= mi;
        sm_acc[tid] = a;
        __syncthreads();
        if (tid < 32) {
            float4 a0 = sm_acc[tid], a1 = sm_acc[tid + 32];
            float4 a2 = sm_acc[tid + 64], a3 = sm_acc[tid + 96];
            int c4 = tid + q * 32;
            float4 b = ((const float4*)bias)[c4];
            float4 v;
            v.x = a0.x + a1.x + a2.x + a3.x + b.x;
            v.y = a0.y + a1.y + a2.y + a3.y + b.y;
            v.z = a0.z + a1.z + a2.z + a3.z + b.z;
            v.w = a0.w + a1.w + a2.w + a3.w + b.w;
            if (RELU) {
                v.x = fmaxf(v.x, 0.f); v.y = fmaxf(v.y, 0.f);
                v.z = fmaxf(v.z, 0.f); v.w = fmaxf(v.w, 0.f);
            }
            ((float4*)(out + (size_t)n * C))[c4] = v;
        }
    }
}

// ---------------- reparameterize: partitionable threefry, XOR-folded lanes (R7-verified) ----------------
__device__ __forceinline__ unsigned rotl32(unsigned x, int d) { return (x << d) | (x >> (32 - d)); }

__device__ __forceinline__ float bits_to_normal(unsigned bits) {
    float f = __uint_as_float((bits >> 9) | 0x3f800000u) - 1.0f;
    const float lo = -0.99999994f;
    float u = fmaxf(lo, f * (1.0f - lo) + lo);
    return 1.41421356237f * erfinvf(u);
}

__global__ void reparam(const float* __restrict__ mu, const float* __restrict__ lv,
                        float* __restrict__ z, int n)
{
    int i = blockIdx.x * blockDim.x + threadIdx.x;
    if (i >= n) return;
    const unsigned ks0 = 0u, ks1 = 1u, ks2 = 0x1BD11BDBu;
    unsigned x0 = 0u + ks0;
    unsigned x1 = (unsigned)i + ks1;
#define TFR(r) { x0 += x1; x1 = rotl32(x1, r); x1 ^= x0; }
    TFR(13) TFR(15) TFR(26) TFR(6)
    x0 += ks1; x1 += ks2 + 1u;
    TFR(17) TFR(29) TFR(16) TFR(24)
    x0 += ks2; x1 += ks0 + 2u;
    TFR(13) TFR(15) TFR(26) TFR(6)
    x0 += ks0; x1 += ks1 + 3u;
    TFR(17) TFR(29) TFR(16) TFR(24)
    x0 += ks1; x1 += ks2 + 4u;
    TFR(13) TFR(15) TFR(26) TFR(6)
    x0 += ks2; x1 += ks0 + 5u;
#undef TFR
    float eps = bits_to_normal(x0 ^ x1);
    z[i] = mu[i] + eps * expf(0.5f * lv[i]);
}

// ---------------- pd prep: row norms + tf32 hi/lo split ----------------
__global__ void rownorm_split(const float* __restrict__ r,
                              float* __restrict__ phi, float* __restrict__ plo)
{
    int row = (blockIdx.x * blockDim.x + threadIdx.x) >> 5;
    int lane = threadIdx.x & 31;
    if (row >= NN) return;
    float s = 0.f;
#pragma unroll
    for (int c = lane; c < 128; c += 32) {
        float v = r[(size_t)row * 128 + c];
        s += v * v;
        float hi, lo;
        split_tf32(v, hi, lo);
        phi[(size_t)row * 128 + c] = hi;
        plo[(size_t)row * 128 + c] = lo;
    }
#pragma unroll
    for (int o = 16; o; o >>= 1) s += __shfl_xor_sync(0xffffffffu, s, o);
    if (lane == 0) g_sq[row] = s;
}

// ---------------- pd via tf32 split mma (hi*hi + hi*lo + lo*hi) ----------------
__global__ void __launch_bounds__(256)
pd_tc(const float* __restrict__ Rhi, const float* __restrict__ Rlo,
      float* __restrict__ P)
{
    __shared__ float As[128 * PDS];
    __shared__ float Bs[128 * PDS];
    const int tid = threadIdx.x;
    const int wid = tid >> 5, lane = tid & 31;
    const int wm = wid & 1, wn = wid >> 1;
    const int grp = lane >> 2, tig = lane & 3;
    const int rb = blockIdx.y * 128, cb = blockIdx.x * 128;

    float acc[4][4][4];
#pragma unroll
    for (int mt = 0; mt < 4; mt++)
#pragma unroll
        for (int nt = 0; nt < 4; nt++)
#pragma unroll
            for (int q = 0; q < 4; q++) acc[mt][nt][q] = 0.f;

    for (int kt = 0; kt < 8; kt++) {
#pragma unroll
        for (int l = 0; l < 2; l++) {
            int idx = tid + l * 256;
            int row = idx >> 2, q = idx & 3;
            int gr = rb + row;
            int gc = cb + row;
            float4 h4 = make_float4(0.f, 0.f, 0.f, 0.f), l4 = h4;
            if (gr < NN) {
                h4 = *(const float4*)&Rhi[(size_t)gr * 128 + kt * 16 + q * 4];
                l4 = *(const float4*)&Rlo[(size_t)gr * 128 + kt * 16 + q * 4];
            }
            float* dp = &As[row * PDS + q * 8];
            dp[0] = h4.x; dp[1] = l4.x; dp[2] = h4.y; dp[3] = l4.y;
            dp[4] = h4.z; dp[5] = l4.z; dp[6] = h4.w; dp[7] = l4.w;
            h4 = make_float4(0.f, 0.f, 0.f, 0.f); l4 = h4;
            if (gc < NN) {
                h4 = *(const float4*)&Rhi[(size_t)gc * 128 + kt * 16 + q * 4];
                l4 = *(const float4*)&Rlo[(size_t)gc * 128 + kt * 16 + q * 4];
            }
            dp = &Bs[row * PDS + q * 8];
            dp[0] = h4.x; dp[1] = l4.x; dp[2] = h4.y; dp[3] = l4.y;
            dp[4] = h4.z; dp[5] = l4.z; dp[6] = h4.w; dp[7] = l4.w;
        }
        __syncthreads();
#pragma unroll
        for (int kc = 0; kc < 16; kc += 8) {
            unsigned ahi[4][4], alo[4][4];
#pragma unroll
            for (int mt = 0; mt < 4; mt++) {
                int r0 = (wm * 64 + mt * 16 + grp) * PDS + (kc + tig) * 2;
                int r1 = r0 + 8 * PDS;
                float2 p0 = *(const float2*)&As[r0];
                float2 p1 = *(const float2*)&As[r1];
                float2 p2 = *(const float2*)&As[r0 + 8];
                float2 p3 = *(const float2*)&As[r1 + 8];
                ahi[mt][0] = __float_as_uint(p0.x); alo[mt][0] = __float_as_uint(p0.y);
                ahi[mt][1] = __float_as_uint(p1.x); alo[mt][1] = __float_as_uint(p1.y);
                ahi[mt][2] = __float_as_uint(p2.x); alo[mt][2] = __float_as_uint(p2.y);
                ahi[mt][3] = __float_as_uint(p3.x); alo[mt][3] = __float_as_uint(p3.y);
            }
            unsigned bhi[4][2], blo[4][2];
#pragma unroll
            for (int nt = 0; nt < 4; nt++) {
                int rn = (wn * 32 + nt * 8 + grp) * PDS + (kc + tig) * 2;
                float2 q0 = *(const float2*)&Bs[rn];
                float2 q1 = *(const float2*)&Bs[rn + 8];
                bhi[nt][0] = __float_as_uint(q0.x); blo[nt][0] = __float_as_uint(q0.y);
                bhi[nt][1] = __float_as_uint(q1.x); blo[nt][1] = __float_as_uint(q1.y);
            }
#pragma unroll
            for (int mt = 0; mt < 4; mt++)
#pragma unroll
                for (int nt = 0; nt < 4; nt++) {
                    mma8(acc[mt][nt], ahi[mt][0], ahi[mt][1], ahi[mt][2], ahi[mt][3],
                         bhi[nt][0], bhi[nt][1]);
                    mma8(acc[mt][nt], ahi[mt][0], ahi[mt][1], ahi[mt][2], ahi[mt][3],
                         blo[nt][0], blo[nt][1]);
                    mma8(acc[mt][nt], alo[mt][0], alo[mt][1], alo[mt][2], alo[mt][3],
                         bhi[nt][0], bhi[nt][1]);
                }
        }
        __syncthreads();
    }

#pragma unroll
    for (int mt = 0; mt < 4; mt++) {
        int r0 = rb + wm * 64 + mt * 16 + grp;
        int r1 = r0 + 8;
        float sq0 = (r0 < NN) ? g_sq[r0] : 0.f;
        float sq1 = (r1 < NN) ? g_sq[r1] : 0.f;
#pragma unroll
        for (int nt = 0; nt < 4; nt++) {
            int c = cb + wn * 32 + nt * 8 + tig * 2;
            if (c + 1 < NN) {
                float sc0 = g_sq[c], sc1 = g_sq[c + 1];
                if (r0 < NN) {
                    float2 v;
                    v.x = sqrtf(fmaxf(sq0 + sc0 - 2.f * acc[mt][nt][0], 1e-12f));
                    v.y = sqrtf(fmaxf(sq0 + sc1 - 2.f * acc[mt][nt][1], 1e-12f));
                    *(float2*)&P[(size_t)r0 * NN + c] = v;
                }
                if (r1 < NN) {
                    float2 v;
                    v.x = sqrtf(fmaxf(sq1 + sc0 - 2.f * acc[mt][nt][2], 1e-12f));
                    v.y = sqrtf(fmaxf(sq1 + sc1 - 2.f * acc[mt][nt][3], 1e-12f));
                    *(float2*)&P[(size_t)r1 * NN + c] = v;
                }
            } else if (c < NN) {
                float sc0 = g_sq[c];
                if (r0 < NN) P[(size_t)r0 * NN + c] =
                    sqrtf(fmaxf(sq0 + sc0 - 2.f * acc[mt][nt][0], 1e-12f));
                if (r1 < NN) P[(size_t)r1 * NN + c] =
                    sqrtf(fmaxf(sq1 + sc0 - 2.f * acc[mt][nt][2], 1e-12f));
            }
        }
    }
}

// ---------------- launch ----------------
static inline int divup(int a, int b) { return (a + b - 1) / b; }

extern "C" void kernel_launch(void* const* d_in, const int* in_sizes, int n_in,
                              void* d_out, int out_size)
{
    const float* x   = (const float*)d_in[0];
    const int*   ei  = (const int*)d_in[1];
    const int E = in_sizes[1] / 2;
    const float* W1  = (const float*)d_in[2];
    const float* a1s = (const float*)d_in[3];
    const float* a1d = (const float*)d_in[4];
    const float* b1  = (const float*)d_in[5];
    const float* W2  = (const float*)d_in[6];
    const float* a2s = (const float*)d_in[7];
    const float* a2d = (const float*)d_in[8];
    const float* b2  = (const float*)d_in[9];
    const float* Wmu = (const float*)d_in[10];
    const float* bmu = (const float*)d_in[11];
    const float* Wlv = (const float*)d_in[12];
    const float* blv = (const float*)d_in[13];
    const float* Wd1 = (const float*)d_in[14];
    const float* bd1 = (const float*)d_in[15];
    const float* Wd2 = (const float*)d_in[16];
    const float* bd2 = (const float*)d_in[17];
    const float* W3  = (const float*)d_in[18];
    const float* a3s = (const float*)d_in[19];
    const float* a3d = (const float*)d_in[20];
    const float* b3  = (const float*)d_in[21];

    float* out     = (float*)d_out;
    float* d_recon = out;
    float* d_mu    = out + (size_t)NN * 128;
    float* d_lv    = d_mu + (size_t)NN * 64;
    float* d_pd    = d_lv + (size_t)NN * 64;

    float *hbuf, *out1, *out2, *zb, *d1b, *d2b;
    cudaGetSymbolAddress((void**)&hbuf, g_hbuf);
    cudaGetSymbolAddress((void**)&out1, g_out1);
    cudaGetSymbolAddress((void**)&out2, g_out2);
    cudaGetSymbolAddress((void**)&zb,   g_zb);
    cudaGetSymbolAddress((void**)&d1b,  g_d1b);
    cudaGetSymbolAddress((void**)&d2b,  g_d2b);

    const int* srcp = ei;
    const int* dstp = ei + E;
    const int ET = E + NN;
    const int EB = divup(ET, 256);

    // ----- CSR build -----
    zero_cnt<<<divup(NN, 256), 256>>>();
    count_k<<<EB, 256>>>(dstp, E);
    scan_k<<<1, 1024>>>();
    scatter_k<<<EB, 256>>>(dstp, E);

    // ----- encoder conv1: 128 -> H*256 -----
    sgemm_tc<<<dim3(8, 79), 256>>>(x, W1, nullptr, hbuf, NN, 1024, 128, 0);
    attn_proj<256, 1024><<<NN, 128>>>(hbuf, a1s, a1d);
    gat_agg<256, 1024, 1><<<NN, 128>>>(srcp, E, hbuf, b1, out1);

    // ----- encoder conv2: 256 -> H*128 -----
    sgemm_tc<<<dim3(4, 79), 256>>>(out1, W2, nullptr, hbuf, NN, 512, 256, 0);
    attn_proj<128, 512><<<NN, 128>>>(hbuf, a2s, a2d);
    gat_agg<128, 512, 1><<<NN, 128>>>(srcp, E, hbuf, b2, out2);

    // ----- mu / logvar heads -----
    sgemm_tc<<<dim3(1, 79), 256>>>(out2, Wmu, bmu, d_mu, NN, 64, 128, 1);
    sgemm_tc<<<dim3(1, 79), 256>>>(out2, Wlv, blv, d_lv, NN, 64, 128, 1);

    // ----- reparameterize -----
    reparam<<<divup(NN * 64, 256), 256>>>(d_mu, d_lv, zb, NN * 64);

    // ----- decoder dense -----
    sgemm_tc<<<dim3(1, 79), 256>>>(zb,  Wd1, bd1, d1b, NN, 128, 64, 2);
    sgemm_tc<<<dim3(2, 79), 256>>>(d1b, Wd2, bd2, d2b, NN, 256, 128, 2);

    // ----- decoder conv3: 256 -> H*128 (no relu) -----
    sgemm_tc<<<dim3(4, 79), 256>>>(d2b, W3, nullptr, hbuf, NN, 512, 256, 0);
    attn_proj<128, 512><<<NN, 128>>>(hbuf, a3s, a3d);
    gat_agg<128, 512, 0><<<NN, 128>>>(srcp, E, hbuf, b3, d_recon);

    // ----- pairwise distances (tf32 split tensor path) -----
    float* phi = hbuf;
    float* plo = hbuf + (size_t)NN * 128;
    rownorm_split<<<divup(NN * 32, 256), 256>>>(d_recon, phi, plo);
    pd_tc<<<dim3(79, 79), 256>>>(phi, plo, d_pd);
}

// round 14
// speedup vs baseline: 1.6324x; 1.2484x over previous
#include <cuda_runtime.h>
#include <math.h>

#define NN 10000
#define EMAX 320000
#define ETMAX (EMAX + NN)

// ---------------- scratch (device globals; no allocation allowed) ----------------
__device__ __align__(16) float g_hbuf[NN * 1024];
__device__ __align__(16) float g_out1[NN * 256];
__device__ __align__(16) float g_out2[NN * 128];
__device__ __align__(16) float g_zb  [NN * 64];
__device__ __align__(16) float g_d1b [NN * 128];
__device__ __align__(16) float g_d2b [NN * 256];
__device__ __align__(16) float g_al  [NN * 4];
__device__ __align__(16) float g_ar  [NN * 4];
__device__ float g_sq  [NN];
__device__ int   g_cnt [NN];
__device__ int   g_off [NN + 1];
__device__ int   g_perm[ETMAX];

#define PDS 40   // smem row stride (floats): 16 k * 2 (hi,lo) + 8 pad

__device__ __forceinline__ void mma8(float* d, unsigned a0, unsigned a1, unsigned a2, unsigned a3,
                                     unsigned b0, unsigned b1)
{
    asm("mma.sync.aligned.m16n8k8.row.col.f32.tf32.tf32.f32 "
        "{%0,%1,%2,%3}, {%4,%5,%6,%7}, {%8,%9}, {%0,%1,%2,%3};\n"
        : "+f"(d[0]), "+f"(d[1]), "+f"(d[2]), "+f"(d[3])
        : "r"(a0), "r"(a1), "r"(a2), "r"(a3), "r"(b0), "r"(b1));
}

__device__ __forceinline__ void split_tf32(float v, float& hi, float& lo)
{
    hi = __uint_as_float(__float_as_uint(v) & 0xFFFFE000u);
    float l = v - hi;
    lo = __uint_as_float(__float_as_uint(l) & 0xFFFFE000u);
}

// ---------------- split-tf32 tensor-core GEMM: C[M,N] = A[M,K] @ B[K,N] ----------------
__global__ void __launch_bounds__(256)
sgemm_tc(const float* __restrict__ A, const float* __restrict__ B,
         const float* __restrict__ bias, float* __restrict__ C,
         int M, int N, int K, int epi)
{
    __shared__ float As[128 * PDS];
    __shared__ float Bs[128 * PDS];
    const int tid = threadIdx.x;
    const int wid = tid >> 5, lane = tid & 31;
    const int wm = wid & 1, wn = wid >> 1;
    const int grp = lane >> 2, tig = lane & 3;
    const int rb = blockIdx.y * 128, cb = blockIdx.x * 128;

    float acc[4][4][4];
#pragma unroll
    for (int mt = 0; mt < 4; mt++)
#pragma unroll
        for (int nt = 0; nt < 4; nt++)
#pragma unroll
            for (int q = 0; q < 4; q++) acc[mt][nt][q] = 0.f;

    for (int k0 = 0; k0 < K; k0 += 16) {
#pragma unroll
        for (int l = 0; l < 2; l++) {
            int idx = tid + l * 256;
            int row = idx >> 2, q = idx & 3;
            int gm = rb + row;
            float4 v = make_float4(0.f, 0.f, 0.f, 0.f);
            if (gm < M) v = *(const float4*)(A + (size_t)gm * K + k0 + q * 4);
            float* dp = &As[row * PDS + q * 8];
            split_tf32(v.x, dp[0], dp[1]);
            split_tf32(v.y, dp[2], dp[3]);
            split_tf32(v.z, dp[4], dp[5]);
            split_tf32(v.w, dp[6], dp[7]);
        }
#pragma unroll
        for (int l = 0; l < 2; l++) {
            int idx = tid + l * 256;
            int kb = idx & 15, n4 = idx >> 4;
            int gn = cb + n4 * 4;
            float4 w = make_float4(0.f, 0.f, 0.f, 0.f);
            if (gn + 3 < N) w = *(const float4*)(B + (size_t)(k0 + kb) * N + gn);
            else if (gn < N) {
                w.x = B[(size_t)(k0 + kb) * N + gn];
                if (gn + 1 < N) w.y = B[(size_t)(k0 + kb) * N + gn + 1];
                if (gn + 2 < N) w.z = B[(size_t)(k0 + kb) * N + gn + 2];
            }
            float hi, lo;
            split_tf32(w.x, hi, lo);
            Bs[(n4 * 4 + 0) * PDS + kb * 2] = hi; Bs[(n4 * 4 + 0) * PDS + kb * 2 + 1] = lo;
            split_tf32(w.y, hi, lo);
            Bs[(n4 * 4 + 1) * PDS + kb * 2] = hi; Bs[(n4 * 4 + 1) * PDS + kb * 2 + 1] = lo;
            split_tf32(w.z, hi, lo);
            Bs[(n4 * 4 + 2) * PDS + kb * 2] = hi; Bs[(n4 * 4 + 2) * PDS + kb * 2 + 1] = lo;
            split_tf32(w.w, hi, lo);
            Bs[(n4 * 4 + 3) * PDS + kb * 2] = hi; Bs[(n4 * 4 + 3) * PDS + kb * 2 + 1] = lo;
        }
        __syncthreads();
#pragma unroll
        for (int kc = 0; kc < 16; kc += 8) {
            unsigned ahi[4][4], alo[4][4];
#pragma unroll
            for (int mt = 0; mt < 4; mt++) {
                int r0 = (wm * 64 + mt * 16 + grp) * PDS + (kc + tig) * 2;
                int r1 = r0 + 8 * PDS;
                float2 p0 = *(const float2*)&As[r0];
                float2 p1 = *(const float2*)&As[r1];
                float2 p2 = *(const float2*)&As[r0 + 8];
                float2 p3 = *(const float2*)&As[r1 + 8];
                ahi[mt][0] = __float_as_uint(p0.x); alo[mt][0] = __float_as_uint(p0.y);
                ahi[mt][1] = __float_as_uint(p1.x); alo[mt][1] = __float_as_uint(p1.y);
                ahi[mt][2] = __float_as_uint(p2.x); alo[mt][2] = __float_as_uint(p2.y);
                ahi[mt][3] = __float_as_uint(p3.x); alo[mt][3] = __float_as_uint(p3.y);
            }
            unsigned bhi[4][2], blo[4][2];
#pragma unroll
            for (int nt = 0; nt < 4; nt++) {
                int rn = (wn * 32 + nt * 8 + grp) * PDS + (kc + tig) * 2;
                float2 q0 = *(const float2*)&Bs[rn];
                float2 q1 = *(const float2*)&Bs[rn + 8];
                bhi[nt][0] = __float_as_uint(q0.x); blo[nt][0] = __float_as_uint(q0.y);
                bhi[nt][1] = __float_as_uint(q1.x); blo[nt][1] = __float_as_uint(q1.y);
            }
#pragma unroll
            for (int mt = 0; mt < 4; mt++)
#pragma unroll
                for (int nt = 0; nt < 4; nt++) {
                    mma8(acc[mt][nt], ahi[mt][0], ahi[mt][1], ahi[mt][2], ahi[mt][3],
                         bhi[nt][0], bhi[nt][1]);
                    mma8(acc[mt][nt], ahi[mt][0], ahi[mt][1], ahi[mt][2], ahi[mt][3],
                         blo[nt][0], blo[nt][1]);
                    mma8(acc[mt][nt], alo[mt][0], alo[mt][1], alo[mt][2], alo[mt][3],
                         bhi[nt][0], bhi[nt][1]);
                }
        }
        __syncthreads();
    }

#pragma unroll
    for (int mt = 0; mt < 4; mt++) {
        int r0 = rb + wm * 64 + mt * 16 + grp;
        int r1 = r0 + 8;
#pragma unroll
        for (int nt = 0; nt < 4; nt++) {
            int c = cb + wn * 32 + nt * 8 + tig * 2;
            if (c >= N) continue;
            float b0 = 0.f, b1 = 0.f;
            if (epi >= 1) { b0 = bias[c]; b1 = bias[c + 1]; }
            if (r0 < M) {
                float v0 = acc[mt][nt][0] + b0, v1 = acc[mt][nt][1] + b1;
                if (epi == 2) { v0 = fmaxf(v0, 0.f); v1 = fmaxf(v1, 0.f); }
                float2 v = make_float2(v0, v1);
                *(float2*)&C[(size_t)r0 * N + c] = v;
            }
            if (r1 < M) {
                float v0 = acc[mt][nt][2] + b0, v1 = acc[mt][nt][3] + b1;
                if (epi == 2) { v0 = fmaxf(v0, 0.f); v1 = fmaxf(v1, 0.f); }
                float2 v = make_float2(v0, v1);
                *(float2*)&C[(size_t)r1 * N + c] = v;
            }
        }
    }
}

// ---------------- attention projections ----------------
template <int C, int HC>
__global__ void attn_proj(const float* __restrict__ h, const float* __restrict__ as_,
                          const float* __restrict__ ad_)
{
    int n = blockIdx.x;
    int head = threadIdx.x >> 5, lane = threadIdx.x & 31;
    const float* hp = h + (size_t)n * HC + head * C;
    const float* sp = as_ + head * C;
    const float* dp = ad_ + head * C;
    float ss = 0.f, sd = 0.f;
#pragma unroll
    for (int c = lane; c < C; c += 32) {
        float v = hp[c];
        ss += v * sp[c];
        sd += v * dp[c];
    }
#pragma unroll
    for (int o = 16; o; o >>= 1) {
        ss += __shfl_xor_sync(0xffffffffu, ss, o);
        sd += __shfl_xor_sync(0xffffffffu, sd, o);
    }
    if (lane == 0) { g_al[n * 4 + head] = ss; g_ar[n * 4 + head] = sd; }
}

// ---------------- CSR build ----------------
__global__ void zero_cnt()
{
    int t = blockIdx.x * blockDim.x + threadIdx.x;
    if (t < NN) g_cnt[t] = 0;
}

__global__ void count_k(const int* __restrict__ dst, int E)
{
    int i = blockIdx.x * blockDim.x + threadIdx.x;
    if (i >= E + NN) return;
    int d = (i < E) ? dst[i] : (i - E);
    atomicAdd(&g_cnt[d], 1);
}

__global__ void scan_k()
{
    __shared__ int wsum[32];
    const int PER = 10;
    int tid = threadIdx.x;
    int lane = tid & 31, wid = tid >> 5;
    int base = tid * PER;
    int v[PER];
    int s = 0;
#pragma unroll
    for (int q = 0; q < PER; q++) {
        int i = base + q;
        v[q] = (i < NN) ? g_cnt[i] : 0;
        s += v[q];
    }
    int t = s;
#pragma unroll
    for (int o = 1; o < 32; o <<= 1) {
        int u = __shfl_up_sync(0xffffffffu, t, o);
        if (lane >= o) t += u;
    }
    if (lane == 31) wsum[wid] = t;
    __syncthreads();
    if (wid == 0) {
        int w = wsum[lane];
#pragma unroll
        for (int o = 1; o < 32; o <<= 1) {
            int u = __shfl_up_sync(0xffffffffu, w, o);
            if (lane >= o) w += u;
        }
        wsum[lane] = w;
    }
    __syncthreads();
    int excl = t - s + ((wid > 0) ? wsum[wid - 1] : 0);
#pragma unroll
    for (int q = 0; q < PER; q++) {
        int i = base + q;
        if (i < NN) { g_off[i] = excl; g_cnt[i] = excl; }
        excl += v[q];
    }
    if (tid == 1023) g_off[NN] = excl;
}

__global__ void scatter_k(const int* __restrict__ dst, int E)
{
    int i = blockIdx.x * blockDim.x + threadIdx.x;
    if (i >= E + NN) return;
    int d = (i < E) ? dst[i] : (i - E);
    int pos = atomicAdd(&g_cnt[d], 1);
    g_perm[pos] = i;
}

// ---------------- fused GAT aggregation ----------------
template <int C, int HC, int RELU>
__global__ void gat_agg(const int* __restrict__ src, int E,
                        const float* __restrict__ h,
                        const float* __restrict__ bias,
                        float* __restrict__ out)
{
    constexpr int ACC = C / 128;
    __shared__ int    sm_s[128];
    __shared__ float4 sm_w[128];
    __shared__ float4 sred[4];

    int n = blockIdx.x;
    int tid = threadIdx.x;
    int wid = tid >> 5, lane = tid & 31;
    int head = wid;
    int slot = lane;
    int off = g_off[n];
    int deg = g_off[n + 1] - off;

    float4 arn = *(const float4*)&g_ar[n * 4];

    float4 mx = make_float4(-1e30f, -1e30f, -1e30f, -1e30f);
    for (int j = tid; j < deg; j += 128) {
        int e = g_perm[off + j];
        int s = (e < E) ? src[e] : (e - E);
        float4 a = *(const float4*)&g_al[s * 4];
        float l0 = a.x + arn.x; l0 = l0 >= 0.f ? l0 : 0.2f * l0;
        float l1 = a.y + arn.y; l1 = l1 >= 0.f ? l1 : 0.2f * l1;
        float l2 = a.z + arn.z; l2 = l2 >= 0.f ? l2 : 0.2f * l2;
        float l3 = a.w + arn.w; l3 = l3 >= 0.f ? l3 : 0.2f * l3;
        mx.x = fmaxf(mx.x, l0); mx.y = fmaxf(mx.y, l1);
        mx.z = fmaxf(mx.z, l2); mx.w = fmaxf(mx.w, l3);
    }
#pragma unroll
    for (int o = 16; o; o >>= 1) {
        mx.x = fmaxf(mx.x, __shfl_xor_sync(0xffffffffu, mx.x, o));
        mx.y = fmaxf(mx.y, __shfl_xor_sync(0xffffffffu, mx.y, o));
        mx.z = fmaxf(mx.z, __shfl_xor_sync(0xffffffffu, mx.z, o));
        mx.w = fmaxf(mx.w, __shfl_xor_sync(0xffffffffu, mx.w, o));
    }
    if (lane == 0) sred[wid] = mx;
    __syncthreads();
    if (tid == 0) {
        float4 a = sred[0];
#pragma unroll
        for (int w = 1; w < 4; w++) {
            float4 b = sred[w];
            a.x = fmaxf(a.x, b.x); a.y = fmaxf(a.y, b.y);
            a.z = fmaxf(a.z, b.z); a.w = fmaxf(a.w, b.w);
        }
        sred[0] = a;
    }
    __syncthreads();
    mx = sred[0];
    __syncthreads();

    float4 acc[ACC];
#pragma unroll
    for (int q = 0; q < ACC; q++) acc[q] = make_float4(0.f, 0.f, 0.f, 0.f);
    float4 den = make_float4(0.f, 0.f, 0.f, 0.f);
    const float* sm_wf = (const float*)sm_w;

    for (int base = 0; base < deg; base += 128) {
        int cnt = min(128, deg - base);
        int j = base + tid;
        if (j < deg) {
            int e = g_perm[off + j];
            int s = (e < E) ? src[e] : (e - E);
            float4 a = *(const float4*)&g_al[s * 4];
            float l0 = a.x + arn.x; l0 = l0 >= 0.f ? l0 : 0.2f * l0;
            float l1 = a.y + arn.y; l1 = l1 >= 0.f ? l1 : 0.2f * l1;
            float l2 = a.z + arn.z; l2 = l2 >= 0.f ? l2 : 0.2f * l2;
            float l3 = a.w + arn.w; l3 = l3 >= 0.f ? l3 : 0.2f * l3;
            float4 ex = make_float4(expf(l0 - mx.x), expf(l1 - mx.y),
                                    expf(l2 - mx.z), expf(l3 - mx.w));
            den.x += ex.x; den.y += ex.y; den.z += ex.z; den.w += ex.w;
            sm_s[tid] = s;
            sm_w[tid] = ex;
        }
        __syncthreads();
#pragma unroll 4
        for (int j2 = 0; j2 < cnt; j2++) {
            int s = sm_s[j2];
            float w = sm_wf[j2 * 4 + head];
            const float4* hs = (const float4*)(h + (size_t)s * HC + head * C);
#pragma unroll
            for (int q = 0; q < ACC; q++) {
                float4 v = hs[slot + q * 32];
                acc[q].x += w * v.x; acc[q].y += w * v.y;
                acc[q].z += w * v.z; acc[q].w += w * v.w;
            }
        }
        __syncthreads();
    }

#pragma unroll
    for (int o = 16; o; o >>= 1) {
        den.x += __shfl_xor_sync(0xffffffffu, den.x, o);
        den.y += __shfl_xor_sync(0xffffffffu, den.y, o);
        den.z += __shfl_xor_sync(0xffffffffu, den.z, o);
        den.w += __shfl_xor_sync(0xffffffffu, den.w, o);
    }
    if (lane == 0) sred[wid] = den;
    __syncthreads();
    if (tid == 0) {
        float4 a = sred[0];
#pragma unroll
        for (int w = 1; w < 4; w++) {
            float4 b = sred[w];
            a.x += b.x; a.y += b.y; a.z += b.z; a.w += b.w;
        }
        sred[0] = a;
    }
    __syncthreads();
    den = sred[0];
    float d4[4];
    *(float4*)d4 = den;
    float mi = 1.0f / (4.0f * d4[head]);

    float4* sm_acc = sm_w;
#pragma unroll
    for (int q = 0; q < ACC; q++) {
        __syncthreads();
        float4 a = acc[q];
        a.x *= mi; a.y *= mi; a.z *= mi; a.w *= mi;
        sm_acc[tid] = a;
        __syncthreads();
        if (tid < 32) {
            float4 a0 = sm_acc[tid], a1 = sm_acc[tid + 32];
            float4 a2 = sm_acc[tid + 64], a3 = sm_acc[tid + 96];
            int c4 = tid + q * 32;
            float4 b = ((const float4*)bias)[c4];
            float4 v;
            v.x = a0.x + a1.x + a2.x + a3.x + b.x;
            v.y = a0.y + a1.y + a2.y + a3.y + b.y;
            v.z = a0.z + a1.z + a2.z + a3.z + b.z;
            v.w = a0.w + a1.w + a2.w + a3.w + b.w;
            if (RELU) {
                v.x = fmaxf(v.x, 0.f); v.y = fmaxf(v.y, 0.f);
                v.z = fmaxf(v.z, 0.f); v.w = fmaxf(v.w, 0.f);
            }
            ((float4*)(out + (size_t)n * C))[c4] = v;
        }
    }
}

// ---------------- reparameterize ----------------
__device__ __forceinline__ unsigned rotl32(unsigned x, int d) { return (x << d) | (x >> (32 - d)); }

__device__ __forceinline__ float bits_to_normal(unsigned bits) {
    float f = __uint_as_float((bits >> 9) | 0x3f800000u) - 1.0f;
    const float lo = -0.99999994f;
    float u = fmaxf(lo, f * (1.0f - lo) + lo);
    return 1.41421356237f * erfinvf(u);
}

__global__ void reparam(const float* __restrict__ mu, const float* __restrict__ lv,
                        float* __restrict__ z, int n)
{
    int i = blockIdx.x * blockDim.x + threadIdx.x;
    if (i >= n) return;
    const unsigned ks0 = 0u, ks1 = 1u, ks2 = 0x1BD11BDBu;
    unsigned x0 = 0u + ks0;
    unsigned x1 = (unsigned)i + ks1;
#define TFR(r) { x0 += x1; x1 = rotl32(x1, r); x1 ^= x0; }
    TFR(13) TFR(15) TFR(26) TFR(6)
    x0 += ks1; x1 += ks2 + 1u;
    TFR(17) TFR(29) TFR(16) TFR(24)
    x0 += ks2; x1 += ks0 + 2u;
    TFR(13) TFR(15) TFR(26) TFR(6)
    x0 += ks0; x1 += ks1 + 3u;
    TFR(17) TFR(29) TFR(16) TFR(24)
    x0 += ks1; x1 += ks2 + 4u;
    TFR(13) TFR(15) TFR(26) TFR(6)
    x0 += ks2; x1 += ks0 + 5u;
#undef TFR
    float eps = bits_to_normal(x0 ^ x1);
    z[i] = mu[i] + eps * expf(0.5f * lv[i]);
}

// ---------------- pd prep: row norms + tf32 hi/lo split ----------------
__global__ void rownorm_split(const float* __restrict__ r,
                              float* __restrict__ phi, float* __restrict__ plo)
{
    int row = (blockIdx.x * blockDim.x + threadIdx.x) >> 5;
    int lane = threadIdx.x & 31;
    if (row >= NN) return;
    float s = 0.f;
#pragma unroll
    for (int c = lane; c < 128; c += 32) {
        float v = r[(size_t)row * 128 + c];
        s += v * v;
        float hi, lo;
        split_tf32(v, hi, lo);
        phi[(size_t)row * 128 + c] = hi;
        plo[(size_t)row * 128 + c] = lo;
    }
#pragma unroll
    for (int o = 16; o; o >>= 1) s += __shfl_xor_sync(0xffffffffu, s, o);
    if (lane == 0) g_sq[row] = s;
}

// ---------------- pd via tf32 split mma, UPPER-TRIANGLE blocks + mirrored write ----------------
#define TRS 132  // transpose staging row stride (floats)

__global__ void __launch_bounds__(256)
pd_tc(const float* __restrict__ Rhi, const float* __restrict__ Rlo,
      float* __restrict__ P)
{
    const int bx = blockIdx.x, by = blockIdx.y;
    if (by > bx) return;                       // symmetric: compute upper triangle only
    __shared__ float sm[10240];                // 40 KB: As|Bs in mainloop, transpose stage after
    float* As = sm;
    float* Bs = sm + 5120;
    const int tid = threadIdx.x;
    const int wid = tid >> 5, lane = tid & 31;
    const int wm = wid & 1, wn = wid >> 1;
    const int grp = lane >> 2, tig = lane & 3;
    const int rb = by * 128, cb = bx * 128;

    float acc[4][4][4];
#pragma unroll
    for (int mt = 0; mt < 4; mt++)
#pragma unroll
        for (int nt = 0; nt < 4; nt++)
#pragma unroll
            for (int q = 0; q < 4; q++) acc[mt][nt][q] = 0.f;

    for (int kt = 0; kt < 8; kt++) {
#pragma unroll
        for (int l = 0; l < 2; l++) {
            int idx = tid + l * 256;
            int row = idx >> 2, q = idx & 3;
            int gr = rb + row;
            int gc = cb + row;
            float4 h4 = make_float4(0.f, 0.f, 0.f, 0.f), l4 = h4;
            if (gr < NN) {
                h4 = *(const float4*)&Rhi[(size_t)gr * 128 + kt * 16 + q * 4];
                l4 = *(const float4*)&Rlo[(size_t)gr * 128 + kt * 16 + q * 4];
            }
            float* dp = &As[row * PDS + q * 8];
            dp[0] = h4.x; dp[1] = l4.x; dp[2] = h4.y; dp[3] = l4.y;
            dp[4] = h4.z; dp[5] = l4.z; dp[6] = h4.w; dp[7] = l4.w;
            h4 = make_float4(0.f, 0.f, 0.f, 0.f); l4 = h4;
            if (gc < NN) {
                h4 = *(const float4*)&Rhi[(size_t)gc * 128 + kt * 16 + q * 4];
                l4 = *(const float4*)&Rlo[(size_t)gc * 128 + kt * 16 + q * 4];
            }
            dp = &Bs[row * PDS + q * 8];
            dp[0] = h4.x; dp[1] = l4.x; dp[2] = h4.y; dp[3] = l4.y;
            dp[4] = h4.z; dp[5] = l4.z; dp[6] = h4.w; dp[7] = l4.w;
        }
        __syncthreads();
#pragma unroll
        for (int kc = 0; kc < 16; kc += 8) {
            unsigned ahi[4][4], alo[4][4];
#pragma unroll
            for (int mt = 0; mt < 4; mt++) {
                int r0 = (wm * 64 + mt * 16 + grp) * PDS + (kc + tig) * 2;
                int r1 = r0 + 8 * PDS;
                float2 p0 = *(const float2*)&As[r0];
                float2 p1 = *(const float2*)&As[r1];
                float2 p2 = *(const float2*)&As[r0 + 8];
                float2 p3 = *(const float2*)&As[r1 + 8];
                ahi[mt][0] = __float_as_uint(p0.x); alo[mt][0] = __float_as_uint(p0.y);
                ahi[mt][1] = __float_as_uint(p1.x); alo[mt][1] = __float_as_uint(p1.y);
                ahi[mt][2] = __float_as_uint(p2.x); alo[mt][2] = __float_as_uint(p2.y);
                ahi[mt][3] = __float_as_uint(p3.x); alo[mt][3] = __float_as_uint(p3.y);
            }
            unsigned bhi[4][2], blo[4][2];
#pragma unroll
            for (int nt = 0; nt < 4; nt++) {
                int rn = (wn * 32 + nt * 8 + grp) * PDS + (kc + tig) * 2;
                float2 q0 = *(const float2*)&Bs[rn];
                float2 q1 = *(const float2*)&Bs[rn + 8];
                bhi[nt][0] = __float_as_uint(q0.x); blo[nt][0] = __float_as_uint(q0.y);
                bhi[nt][1] = __float_as_uint(q1.x); blo[nt][1] = __float_as_uint(q1.y);
            }
#pragma unroll
            for (int mt = 0; mt < 4; mt++)
#pragma unroll
                for (int nt = 0; nt < 4; nt++) {
                    mma8(acc[mt][nt], ahi[mt][0], ahi[mt][1], ahi[mt][2], ahi[mt][3],
                         bhi[nt][0], bhi[nt][1]);
                    mma8(acc[mt][nt], ahi[mt][0], ahi[mt][1], ahi[mt][2], ahi[mt][3],
                         blo[nt][0], blo[nt][1]);
                    mma8(acc[mt][nt], alo[mt][0], alo[mt][1], alo[mt][2], alo[mt][3],
                         bhi[nt][0], bhi[nt][1]);
                }
        }
        __syncthreads();
    }

    // convert acc -> distances in place
#pragma unroll
    for (int mt = 0; mt < 4; mt++) {
        int r0 = rb + wm * 64 + mt * 16 + grp;
        int r1 = r0 + 8;
        float sq0 = (r0 < NN) ? g_sq[r0] : 0.f;
        float sq1 = (r1 < NN) ? g_sq[r1] : 0.f;
#pragma unroll
        for (int nt = 0; nt < 4; nt++) {
            int c = cb + wn * 32 + nt * 8 + tig * 2;
            float sc0 = (c < NN) ? g_sq[c] : 0.f;
            float sc1 = (c + 1 < NN) ? g_sq[c + 1] : 0.f;
            acc[mt][nt][0] = sqrtf(fmaxf(sq0 + sc0 - 2.f * acc[mt][nt][0], 1e-12f));
            acc[mt][nt][1] = sqrtf(fmaxf(sq0 + sc1 - 2.f * acc[mt][nt][1], 1e-12f));
            acc[mt][nt][2] = sqrtf(fmaxf(sq1 + sc0 - 2.f * acc[mt][nt][2], 1e-12f));
            acc[mt][nt][3] = sqrtf(fmaxf(sq1 + sc1 - 2.f * acc[mt][nt][3], 1e-12f));
        }
    }

    // direct (upper) write
#pragma unroll
    for (int mt = 0; mt < 4; mt++) {
        int r0 = rb + wm * 64 + mt * 16 + grp;
        int r1 = r0 + 8;
#pragma unroll
        for (int nt = 0; nt < 4; nt++) {
            int c = cb + wn * 32 + nt * 8 + tig * 2;
            if (c + 1 < NN) {
                if (r0 < NN) *(float2*)&P[(size_t)r0 * NN + c] =
                    make_float2(acc[mt][nt][0], acc[mt][nt][1]);
                if (r1 < NN) *(float2*)&P[(size_t)r1 * NN + c] =
                    make_float2(acc[mt][nt][2], acc[mt][nt][3]);
            } else if (c < NN) {
                if (r0 < NN) P[(size_t)r0 * NN + c] = acc[mt][nt][0];
                if (r1 < NN) P[(size_t)r1 * NN + c] = acc[mt][nt][2];
            }
        }
    }

    // mirrored (lower) write via smem transpose, two 64-column halves
    if (bx != by) {
        float (*T)[TRS] = (float(*)[TRS])sm;    // 64 x 132 = 33792 B
#pragma unroll
        for (int half = 0; half < 2; half++) {
            __syncthreads();
            if ((wn >> 1) == half) {
#pragma unroll
                for (int mt = 0; mt < 4; mt++) {
                    int r0l = wm * 64 + mt * 16 + grp;
                    int r1l = r0l + 8;
#pragma unroll
                    for (int nt = 0; nt < 4; nt++) {
                        int cl = wn * 32 + nt * 8 + tig * 2 - half * 64;
                        T[cl][r0l]     = acc[mt][nt][0];
                        T[cl + 1][r0l] = acc[mt][nt][1];
                        T[cl][r1l]     = acc[mt][nt][2];
                        T[cl + 1][r1l] = acc[mt][nt][3];
                    }
                }
            }
            __syncthreads();
            int row = tid >> 2, q = tid & 3;
            int c = cb + half * 64 + row;
            if (c < NN) {
#pragma unroll
                for (int k = 0; k < 8; k++) {
                    int r = rb + q * 32 + k * 4;
                    if (r < NN) {          // NN % 4 == 0 -> full float4 valid
                        float4 v = make_float4(T[row][q * 32 + k * 4 + 0],
                                               T[row][q * 32 + k * 4 + 1],
                                               T[row][q * 32 + k * 4 + 2],
                                               T[row][q * 32 + k * 4 + 3]);
                        *(float4*)&P[(size_t)c * NN + r] = v;
                    }
                }
            }
        }
    }
}

// ---------------- launch ----------------
static inline int divup(int a, int b) { return (a + b - 1) / b; }

extern "C" void kernel_launch(void* const* d_in, const int* in_sizes, int n_in,
                              void* d_out, int out_size)
{
    const float* x   = (const float*)d_in[0];
    const int*   ei  = (const int*)d_in[1];
    const int E = in_sizes[1] / 2;
    const float* W1  = (const float*)d_in[2];
    const float* a1s = (const float*)d_in[3];
    const float* a1d = (const float*)d_in[4];
    const float* b1  = (const float*)d_in[5];
    const float* W2  = (const float*)d_in[6];
    const float* a2s = (const float*)d_in[7];
    const float* a2d = (const float*)d_in[8];
    const float* b2  = (const float*)d_in[9];
    const float* Wmu = (const float*)d_in[10];
    const float* bmu = (const float*)d_in[11];
    const float* Wlv = (const float*)d_in[12];
    const float* blv = (const float*)d_in[13];
    const float* Wd1 = (const float*)d_in[14];
    const float* bd1 = (const float*)d_in[15];
    const float* Wd2 = (const float*)d_in[16];
    const float* bd2 = (const float*)d_in[17];
    const float* W3  = (const float*)d_in[18];
    const float* a3s = (const float*)d_in[19];
    const float* a3d = (const float*)d_in[20];
    const float* b3  = (const float*)d_in[21];

    float* out     = (float*)d_out;
    float* d_recon = out;
    float* d_mu    = out + (size_t)NN * 128;
    float* d_lv    = d_mu + (size_t)NN * 64;
    float* d_pd    = d_lv + (size_t)NN * 64;

    float *hbuf, *out1, *out2, *zb, *d1b, *d2b;
    cudaGetSymbolAddress((void**)&hbuf, g_hbuf);
    cudaGetSymbolAddress((void**)&out1, g_out1);
    cudaGetSymbolAddress((void**)&out2, g_out2);
    cudaGetSymbolAddress((void**)&zb,   g_zb);
    cudaGetSymbolAddress((void**)&d1b,  g_d1b);
    cudaGetSymbolAddress((void**)&d2b,  g_d2b);

    const int* srcp = ei;
    const int* dstp = ei + E;
    const int ET = E + NN;
    const int EB = divup(ET, 256);

    // ----- CSR build -----
    zero_cnt<<<divup(NN, 256), 256>>>();
    count_k<<<EB, 256>>>(dstp, E);
    scan_k<<<1, 1024>>>();
    scatter_k<<<EB, 256>>>(dstp, E);

    // ----- encoder conv1: 128 -> H*256 -----
    sgemm_tc<<<dim3(8, 79), 256>>>(x, W1, nullptr, hbuf, NN, 1024, 128, 0);
    attn_proj<256, 1024><<<NN, 128>>>(hbuf, a1s, a1d);
    gat_agg<256, 1024, 1><<<NN, 128>>>(srcp, E, hbuf, b1, out1);

    // ----- encoder conv2: 256 -> H*128 -----
    sgemm_tc<<<dim3(4, 79), 256>>>(out1, W2, nullptr, hbuf, NN, 512, 256, 0);
    attn_proj<128, 512><<<NN, 128>>>(hbuf, a2s, a2d);
    gat_agg<128, 512, 1><<<NN, 128>>>(srcp, E, hbuf, b2, out2);

    // ----- mu / logvar heads -----
    sgemm_tc<<<dim3(1, 79), 256>>>(out2, Wmu, bmu, d_mu, NN, 64, 128, 1);
    sgemm_tc<<<dim3(1, 79), 256>>>(out2, Wlv, blv, d_lv, NN, 64, 128, 1);

    // ----- reparameterize -----
    reparam<<<divup(NN * 64, 256), 256>>>(d_mu, d_lv, zb, NN * 64);

    // ----- decoder dense -----
    sgemm_tc<<<dim3(1, 79), 256>>>(zb,  Wd1, bd1, d1b, NN, 128, 64, 2);
    sgemm_tc<<<dim3(2, 79), 256>>>(d1b, Wd2, bd2, d2b, NN, 256, 128, 2);

    // ----- decoder conv3: 256 -> H*128 (no relu) -----
    sgemm_tc<<<dim3(4, 79), 256>>>(d2b, W3, nullptr, hbuf, NN, 512, 256, 0);
    attn_proj<128, 512><<<NN, 128>>>(hbuf, a3s, a3d);
    gat_agg<128, 512, 0><<<NN, 128>>>(srcp, E, hbuf, b3, d_recon);

    // ----- pairwise distances (tf32 split, symmetric upper-triangle) -----
    float* phi = hbuf;
    float* plo = hbuf + (size_t)NN * 128;
    rownorm_split<<<divup(NN * 32, 256), 256>>>(d_recon, phi, plo);
    pd_tc<<<dim3(79, 79), 256>>>(phi, plo, d_pd);
}